// round 14
// baseline (speedup 1.0000x reference)
#include <cuda_runtime.h>
#include <cuda.h>
#include <cstdint>

#define BQ 16
#define LQ 2048
#define LP 2050
#define OQ 512
#define NG 1536
#define NG2 3072
#define D0 512
#define D1 1024

#if defined(__CUDA_ARCH_FEAT_SM103_ALL) || defined(__CUDA_ARCH_FEAT_SM100_ALL)
#define HAS_TCGEN05 1
#else
#define HAS_TCGEN05 0
#endif

// ---------------- device scratch ----------------
static __device__ float g_xp0[(size_t)BQ * LP * D0];
static __device__ float g_xp1[(size_t)BQ * LP * D1];
static __device__ float g_gates[(size_t)BQ * LQ * NG2];
static __device__ float g_wt0[(size_t)NG2 * 3 * D0];
static __device__ float g_wt1[(size_t)NG2 * 3 * D1];
// scan scratch: 16384 chains x 16 chunks
static __device__ float g_P[262144];
static __device__ float g_Q[262144];
static __device__ float g_cin[262144];

__device__ __forceinline__ float tf32r(float v) {
    uint32_t u;
    asm("cvt.rna.tf32.f32 %0, %1;" : "=r"(u) : "f"(v));
    return __uint_as_float(u);
}
__device__ __forceinline__ float sig_f(float x) {
    return __fdividef(1.f, 1.f + __expf(-x));
}
__device__ __forceinline__ float tanh_f(float x) {
    return __fdividef(2.f, 1.f + __expf(-2.f * x)) - 1.f;
}

// ---------------- setup kernels ----------------
__global__ void pad_x_kernel(const float* __restrict__ x) {
    int idx = blockIdx.x * blockDim.x + threadIdx.x;
    if (idx >= BQ * LP * D0) return;
    int b = idx / (LP * D0);
    int rem = idx - b * (LP * D0);
    int tt = rem >> 9;
    int c = rem & 511;
    float v = 0.f;
    if (tt >= 1 && tt <= LQ) v = x[((size_t)b * LQ + (tt - 1)) * D0 + c];
    g_xp0[idx] = tf32r(v);
}

__global__ void zero_xp1_bounds_kernel() {
    int idx = blockIdx.x * blockDim.x + threadIdx.x;
    if (idx >= BQ * 2 * D1) return;
    int b = idx / (2 * D1);
    int r = (idx >> 10) & 1;
    int c = idx & 1023;
    g_xp1[((size_t)b * LP + (r ? (LP - 1) : 0)) * D1 + c] = 0.f;
}

// coalesced weight transpose: one output row per block via smem staging
__global__ void __launch_bounds__(256) wtrans_kernel(const float* __restrict__ wf,
                                                     const float* __restrict__ wr,
                                                     float* __restrict__ dst, int Din) {
    __shared__ float smt[3072];
    int row = blockIdx.x;
    int K3 = 3 * Din;
    const float* w = (row < NG) ? wf : wr;
    int oc = (row < NG) ? row : row - NG;
    const float* src = w + (size_t)oc * K3;
    for (int j2 = threadIdx.x; j2 < K3; j2 += 256) {
        int i = j2 / 3;
        int k = j2 - 3 * i;
        smt[k * Din + i] = tf32r(src[j2]);
    }
    __syncthreads();
    float* drow = dst + (size_t)row * K3;
    for (int j = threadIdx.x; j < K3; j += 256) drow[j] = smt[j];
}

// ---------------- ptx helpers ----------------
__device__ __forceinline__ uint32_t elect1() {
    uint32_t p;
    asm volatile("{ .reg .pred p; elect.sync _|p, 0xFFFFFFFF; selp.b32 %0, 1, 0, p; }" : "=r"(p));
    return p;
}
__device__ __forceinline__ void mbar_init(uint32_t a, uint32_t c) {
    asm volatile("mbarrier.init.shared.b64 [%0], %1;" ::"r"(a), "r"(c) : "memory");
}
__device__ __forceinline__ void mbar_expect(uint32_t a, uint32_t b) {
    asm volatile("mbarrier.arrive.expect_tx.shared.b64 _, [%0], %1;" ::"r"(a), "r"(b) : "memory");
}
__device__ __forceinline__ void mbar_wait(uint32_t a, uint32_t ph) {
    asm volatile(
        "{ .reg .pred P; LW_%=: mbarrier.try_wait.parity.acquire.cta.shared::cta.b64 P, [%0], %1, 0x989680;"
        " @P bra LD_%=; bra LW_%=; LD_%=: }" ::"r"(a), "r"(ph) : "memory");
}
__device__ __forceinline__ void mbar_wait_rlx(uint32_t a, uint32_t ph) {
    asm volatile(
        "{ .reg .pred P; LW_%=: mbarrier.try_wait.parity.relaxed.cta.shared::cta.b64 P, [%0], %1, 0x989680;"
        " @P bra LD_%=; bra LW_%=; LD_%=: }" ::"r"(a), "r"(ph) : "memory");
}
__device__ __forceinline__ void tma2d(uint32_t dst, const CUtensorMap* tm, int x, int y, uint32_t mbar) {
    asm volatile(
        "cp.async.bulk.tensor.2d.shared::cta.global.tile.mbarrier::complete_tx::bytes "
        "[%0], [%1, {%2, %3}], [%4];" ::"r"(dst), "l"(tm), "r"(x), "r"(y), "r"(mbar)
        : "memory");
}
__device__ __forceinline__ uint64_t mkdesc(uint32_t addr) {
    // SW128, version=1, SBO=64 (1024B), LBO=1 (16B)
    return 0x4000404000010000ULL | ((uint64_t)(addr >> 4) & 0x3FFF);
}
// tf32 idesc: dtype=F32, a/b=TF32, M=128, N=128
#define IDESC_N128 0x8200910u

#if HAS_TCGEN05
__device__ __forceinline__ void mma_tf32_tc(uint32_t d, uint64_t ad, uint64_t bd, uint32_t id, bool acc) {
    uint32_t en = acc ? 1u : 0u;
    asm volatile(
        "{\n\t.reg .pred p;\n\tsetp.ne.u32 p, %5, 0;\n\t"
        "tcgen05.mma.cta_group::1.kind::tf32 [%0], %1, %2, %3, {%4,%4,%4,%4}, p;\n\t}"
        ::"r"(d), "l"(ad), "l"(bd), "r"(id), "r"(0u), "r"(en)
        : "memory");
}
#define TALLOC(sa, n) asm volatile("tcgen05.alloc.cta_group::1.sync.aligned.shared::cta.b32 [%0], %1;" ::"r"(sa), "r"(n) : "memory")
#define TDEALLOC(t, n) asm volatile("tcgen05.dealloc.cta_group::1.sync.aligned.b32 %0, %1;" ::"r"(t), "r"(n))
#define TRELINQ() asm volatile("tcgen05.relinquish_alloc_permit.cta_group::1.sync.aligned;")
#define TCOMMIT(a) asm volatile("tcgen05.commit.cta_group::1.mbarrier::arrive::one.shared::cluster.b64 [%0];" ::"r"(a) : "memory")
#define TFENCE_AFTER() asm volatile("tcgen05.fence::after_thread_sync;" ::: "memory")
#define TWAIT_LD() asm volatile("tcgen05.wait::ld.sync.aligned;" ::: "memory")
#define TLD_X32(r, a)                                                                           \
    asm volatile(                                                                               \
        "tcgen05.ld.sync.aligned.32x32b.x32.b32 "                                               \
        "{%0, %1, %2, %3, %4, %5, %6, %7, %8, %9, %10, %11, %12, %13, %14, %15, "               \
        " %16, %17, %18, %19, %20, %21, %22, %23, %24, %25, %26, %27, %28, %29, %30, %31}, "    \
        "[%32];"                                                                                \
        : "=r"((r)[0]), "=r"((r)[1]), "=r"((r)[2]), "=r"((r)[3]), "=r"((r)[4]), "=r"((r)[5]),   \
          "=r"((r)[6]), "=r"((r)[7]), "=r"((r)[8]), "=r"((r)[9]), "=r"((r)[10]), "=r"((r)[11]), \
          "=r"((r)[12]), "=r"((r)[13]), "=r"((r)[14]), "=r"((r)[15]), "=r"((r)[16]),            \
          "=r"((r)[17]), "=r"((r)[18]), "=r"((r)[19]), "=r"((r)[20]), "=r"((r)[21]),            \
          "=r"((r)[22]), "=r"((r)[23]), "=r"((r)[24]), "=r"((r)[25]), "=r"((r)[26]),            \
          "=r"((r)[27]), "=r"((r)[28]), "=r"((r)[29]), "=r"((r)[30]), "=r"((r)[31])             \
        : "r"(a))
#endif

// =====================================================================
// PATH A: tcgen05 tf32 GEMM. Tile M=128 x N=128, K-tile 32 (SW128),
// 3-stage 32KB stages (97KB smem), TMEM alloc 256 cols (2 CTAs/SM fit).
// Each CTA does 2 consecutive M-tiles with ping-pong TMEM buffers:
// MMA fills buf(tile1) while epilogue drains buf(tile0).
// =====================================================================
__global__ void __launch_bounds__(192, 2) gemm_tc(
    const __grid_constant__ CUtensorMap dA,
    const __grid_constant__ CUtensorMap dB,
    const float* __restrict__ bf, const float* __restrict__ br,
    float* __restrict__ G, int DinLog, int numKt) {
#if HAS_TCGEN05
    extern __shared__ char smem[];
    uint32_t sb = (uint32_t)__cvta_generic_to_shared(smem);
    const uint32_t TMEMP = sb;
    const uint32_t BARB = sb + 16;   // full[s]=+s*16, empty[s]=+s*16+8
    const uint32_t DONE0 = sb + 64;  // done[tile] = DONE0 + tile*8
    const uint32_t SA = sb + 1024;   // stage: A 16K | B 16K

    int tid = threadIdx.x, lane = tid & 31, wid = tid >> 5;
    int m0 = blockIdx.y << 8;        // 256 rows per CTA (2 tiles of 128)
    int n0 = blockIdx.x << 7;        // 128 cols per CTA
    int Din = 1 << DinLog;
    int bb = m0 >> 11, t0 = m0 & 2047;
    int Rbase = bb * LP + t0;

    if (tid == 0) {
        for (int s = 0; s < 3; s++) {
            mbar_init(BARB + s * 16, 1);
            mbar_init(BARB + s * 16 + 8, 1);
        }
        mbar_init(DONE0, 1);
        mbar_init(DONE0 + 8, 1);
    }
    if (wid == 5) TALLOC(TMEMP, 256);
    __syncthreads();
    uint32_t tmem;
    asm volatile("ld.shared.b32 %0, [%1];" : "=r"(tmem) : "r"(TMEMP));

    if (wid == 4) {                       // TMA producer: 2 tiles x numKt
        if (elect1()) {
            int ph = 1, s = 0;
#pragma unroll 1
            for (int tile = 0; tile < 2; tile++) {
                int Rb = Rbase + tile * 128;
#pragma unroll 1
                for (int kt = 0; kt < numKt; kt++) {
                    mbar_wait_rlx(BARB + s * 16 + 8, ph);
                    mbar_expect(BARB + s * 16, 32768);
                    int j0 = kt << 5;
                    int q = j0 >> DinLog, r = j0 & (Din - 1);
                    tma2d(SA + s * 32768u, &dA, r, Rb + q, BARB + s * 16);
                    tma2d(SA + s * 32768u + 16384u, &dB, j0, n0, BARB + s * 16);
                    if (++s == 3) { s = 0; ph ^= 1; }
                }
            }
        }
    } else if (wid == 5) {                // MMA issuer: 4 dispatches / kt
        if (elect1()) {
            int ph = 0, s = 0;
#pragma unroll 1
            for (int tile = 0; tile < 2; tile++) {
                uint32_t dbase = tmem + tile * 128;
#pragma unroll 1
                for (int kt = 0; kt < numKt; kt++) {
                    mbar_wait_rlx(BARB + s * 16, ph);
                    uint64_t ad = mkdesc(SA + s * 32768u);
                    uint64_t bd = mkdesc(SA + s * 32768u + 16384u);
#pragma unroll
                    for (int ks = 0; ks < 4; ks++) {
                        bool acc = (kt | ks) != 0;
                        mma_tf32_tc(dbase, ad + ks * 2, bd + ks * 2, IDESC_N128, acc);
                    }
                    TCOMMIT(BARB + s * 16 + 8);
                    if (++s == 3) { s = 0; ph ^= 1; }
                }
                TCOMMIT(DONE0 + tile * 8);
            }
        }
    }

    if (wid < 4) {                        // epilogue: drain tile buffers in order
#pragma unroll 1
        for (int tile = 0; tile < 2; tile++) {
            mbar_wait(DONE0 + tile * 8, 0);
            TFENCE_AFTER();
            int mrow = m0 + tile * 128 + wid * 32 + lane;
            float* grow = G + (size_t)mrow * NG2;
#pragma unroll 1
            for (int cb = 0; cb < 4; cb++) {
                uint32_t r[32];
                TLD_X32(r, tmem + tile * 128 + cb * 32);
                TWAIT_LD();
                int nb = n0 + cb * 32;
                int cmod = (nb >= NG) ? nb - NG : nb;
                const float* bias = (nb >= NG) ? (br + cmod) : (bf + cmod);
                bool ist = cmod >= 2 * OQ;
#pragma unroll
                for (int j = 0; j < 32; j += 4) {
                    float v0 = __uint_as_float(r[j + 0]) + bias[j + 0];
                    float v1 = __uint_as_float(r[j + 1]) + bias[j + 1];
                    float v2 = __uint_as_float(r[j + 2]) + bias[j + 2];
                    float v3 = __uint_as_float(r[j + 3]) + bias[j + 3];
                    float4 o4;
                    o4.x = ist ? tanh_f(v0) : sig_f(v0);
                    o4.y = ist ? tanh_f(v1) : sig_f(v1);
                    o4.z = ist ? tanh_f(v2) : sig_f(v2);
                    o4.w = ist ? tanh_f(v3) : sig_f(v3);
                    *(float4*)(grow + nb + j) = o4;
                }
            }
        }
    }
    __syncthreads();
    if (wid == 5) {
        TRELINQ();
        TDEALLOC(tmem, 256);
    }
#endif  // HAS_TCGEN05
}

// =====================================================================
// PATH B: legacy mma.sync tf32 GEMM (fallback when no 103a PTX)
// =====================================================================
__device__ __forceinline__ void mma_tf32_leg(float* d, const uint32_t* a, const uint32_t* b) {
    asm volatile(
        "mma.sync.aligned.m16n8k8.row.col.f32.tf32.tf32.f32 "
        "{%0,%1,%2,%3}, {%4,%5,%6,%7}, {%8,%9}, {%0,%1,%2,%3};"
        : "+f"(d[0]), "+f"(d[1]), "+f"(d[2]), "+f"(d[3])
        : "r"(a[0]), "r"(a[1]), "r"(a[2]), "r"(a[3]), "r"(b[0]), "r"(b[1]));
}

__global__ void __launch_bounds__(256, 2) gemm_legacy(
    const float* __restrict__ A, const float* __restrict__ W,
    const float* __restrict__ bf, const float* __restrict__ br,
    float* __restrict__ G, int Din, int DinLog, int numKt) {
#if !HAS_TCGEN05
    extern __shared__ float sm[];
    const int K3 = Din * 3;
    int tid = threadIdx.x, lane = tid & 31, warp = tid >> 5;
    int wm = warp >> 2, wn = warp & 3;
    int m0 = blockIdx.y << 7, n0 = blockIdx.x << 7;
    int bb = m0 >> 11, t0 = m0 & 2047;
    size_t Rbase = (size_t)bb * LP + t0;
    uint32_t sbase = (uint32_t)__cvta_generic_to_shared(sm);

    float acc[4][4][4];
#pragma unroll
    for (int i = 0; i < 4; i++)
#pragma unroll
        for (int j = 0; j < 4; j++)
#pragma unroll
            for (int k = 0; k < 4; k++) acc[i][j][k] = 0.f;

    auto load_tiles = [&](int s, int kt) {
        int j0 = kt << 5;
        int q = j0 >> DinLog, r = j0 & (Din - 1);
        const float* Ab = A + (Rbase + q) * (size_t)Din + r;
        const float* Bb = W + j0;
        uint32_t aoff = sbase + s * 16384u;
        uint32_t boff = sbase + 32768u + s * 16384u;
#pragma unroll
        for (int u = 0; u < 4; u++) {
            int idx2 = (u << 8) + tid;
            int row = idx2 >> 3, g4 = idx2 & 7;
            uint32_t d = (uint32_t)((row << 5) + ((g4 ^ (row & 7)) << 2)) * 4u;
            const float* sa = Ab + (size_t)row * Din + (g4 << 2);
            const float* sb2 = Bb + (size_t)(n0 + row) * K3 + (g4 << 2);
            asm volatile("cp.async.cg.shared.global [%0], [%1], 16;" ::"r"(aoff + d), "l"(sa));
            asm volatile("cp.async.cg.shared.global [%0], [%1], 16;" ::"r"(boff + d), "l"(sb2));
        }
    };

    load_tiles(0, 0);
    asm volatile("cp.async.commit_group;");
    int r4 = lane >> 2, c4 = lane & 3;

    for (int kt = 0; kt < numKt; kt++) {
        int cur = kt & 1;
        if (kt + 1 < numKt) {
            load_tiles(cur ^ 1, kt + 1);
            asm volatile("cp.async.commit_group;");
            asm volatile("cp.async.wait_group 1;");
        } else {
            asm volatile("cp.async.wait_group 0;");
        }
        __syncthreads();
        const float* As_ = sm + cur * 4096;
        const float* Bs_ = sm + 8192 + cur * 4096;
#pragma unroll
        for (int kk = 0; kk < 4; kk++) {
            int g0 = ((2 * kk) ^ r4) << 2, g1 = ((2 * kk + 1) ^ r4) << 2;
            uint32_t a[4][4], bq[4][2];
#pragma unroll
            for (int mi = 0; mi < 4; mi++) {
                int row = (wm << 6) + (mi << 4) + r4;
                a[mi][0] = __float_as_uint(As_[(row << 5) + g0 + c4]);
                a[mi][1] = __float_as_uint(As_[((row + 8) << 5) + g0 + c4]);
                a[mi][2] = __float_as_uint(As_[(row << 5) + g1 + c4]);
                a[mi][3] = __float_as_uint(As_[((row + 8) << 5) + g1 + c4]);
            }
#pragma unroll
            for (int ni = 0; ni < 4; ni++) {
                int row = (wn << 5) + (ni << 3) + r4;
                bq[ni][0] = __float_as_uint(Bs_[(row << 5) + g0 + c4]);
                bq[ni][1] = __float_as_uint(Bs_[(row << 5) + g1 + c4]);
            }
#pragma unroll
            for (int mi = 0; mi < 4; mi++)
#pragma unroll
                for (int ni = 0; ni < 4; ni++) mma_tf32_leg(acc[mi][ni], a[mi], bq[ni]);
        }
        __syncthreads();
    }

#pragma unroll
    for (int mi = 0; mi < 4; mi++) {
        int mrow = m0 + (wm << 6) + (mi << 4) + r4;
#pragma unroll
        for (int ni = 0; ni < 4; ni++) {
            int n = n0 + (wn << 5) + (ni << 3) + (c4 << 1);
            int cmod = (n >= NG) ? n - NG : n;
            float bias0 = (n >= NG) ? br[n - NG] : bf[n];
            float bias1 = (n >= NG) ? br[n - NG + 1] : bf[n + 1];
            float v0 = acc[mi][ni][0] + bias0;
            float v1 = acc[mi][ni][1] + bias1;
            float v2 = acc[mi][ni][2] + bias0;
            float v3 = acc[mi][ni][3] + bias1;
            bool is_tanh = (cmod >= 2 * OQ);
            float a0 = is_tanh ? tanh_f(v0) : sig_f(v0);
            float a1 = is_tanh ? tanh_f(v1) : sig_f(v1);
            float a2 = is_tanh ? tanh_f(v2) : sig_f(v2);
            float a3 = is_tanh ? tanh_f(v3) : sig_f(v3);
            *(float2*)(G + (size_t)mrow * NG2 + n) = make_float2(a0, a1);
            *(float2*)(G + (size_t)(mrow + 8) * NG2 + n) = make_float2(a2, a3);
        }
    }
#endif  // !HAS_TCGEN05
}

// ---------------- 3-phase fo-pool scan (16x parallelism) ----------------
__global__ void __launch_bounds__(256) scanA_kernel(const float* __restrict__ Gt) {
    int idx = blockIdx.x * 256 + threadIdx.x;   // [0, 262144)
    int chain = idx & 16383;
    int q = idx >> 14;
    int dir = chain >> 13, b = (chain >> 9) & 15, ch = chain & 511;
    const float* g = Gt + (size_t)b * LQ * NG2 + dir * NG + ch;
    float c = 0.f, Pp = 1.f;
    int s0 = q << 7;
    for (int su = 0; su < 128; su += 8) {
        float fv[8], zv[8];
#pragma unroll
        for (int u = 0; u < 8; u++) {
            int s = s0 + su + u;
            int t = dir ? (LQ - 1 - s) : s;
            size_t o = (size_t)t * NG2;
            fv[u] = g[o];
            zv[u] = g[o + 1024];
        }
#pragma unroll
        for (int u = 0; u < 8; u++) {
            Pp *= fv[u];
            c = fv[u] * (c - zv[u]) + zv[u];
        }
    }
    g_P[idx] = Pp;
    g_Q[idx] = c;
}

__global__ void __launch_bounds__(256) scanB_kernel() {
    int chain = blockIdx.x * 256 + threadIdx.x;  // [0, 16384)
    float c = 0.f;
#pragma unroll
    for (int q = 0; q < 16; q++) {
        int id = (q << 14) + chain;
        g_cin[id] = c;
        c = g_P[id] * c + g_Q[id];
    }
}

__global__ void __launch_bounds__(256) scanC_kernel(
    const float* __restrict__ Gt, float* __restrict__ dst, int rowsPerB, int tOff,
    float* __restrict__ hdst, float* __restrict__ cdst, int doRound) {
    int idx = blockIdx.x * 256 + threadIdx.x;   // [0, 262144)
    int chain = idx & 16383;
    int q = idx >> 14;
    int dir = chain >> 13, b = (chain >> 9) & 15, ch = chain & 511;
    const float* g = Gt + (size_t)b * LQ * NG2 + dir * NG + ch;
    int cc = (dir << 9) + ch;
    float* d = dst + ((size_t)b * rowsPerB + tOff) * 1024 + cc;
    float c = g_cin[idx];
    float hl = 0.f, cl = 0.f;
    int s0 = q << 7;
    for (int su = 0; su < 128; su += 8) {
        float fv[8], ov[8], zv[8];
#pragma unroll
        for (int u = 0; u < 8; u++) {
            int s = s0 + su + u;
            int t = dir ? (LQ - 1 - s) : s;
            size_t o = (size_t)t * NG2;
            fv[u] = g[o];
            ov[u] = g[o + 512];
            zv[u] = g[o + 1024];
        }
#pragma unroll
        for (int u = 0; u < 8; u++) {
            int s = s0 + su + u;
            int t = dir ? (LQ - 1 - s) : s;
            c = fv[u] * (c - zv[u]) + zv[u];
            float h = c * ov[u];
            d[(size_t)t * 1024] = doRound ? tf32r(h) : h;
            if ((dir == 0 && s == LQ - 1) || (dir == 1 && s == 0)) { hl = h; cl = c; }
        }
    }
    if ((dir == 0 && q == 15) || (dir == 1 && q == 0)) {
        hdst[b * 1024 + cc] = hl;
        cdst[b * 1024 + cc] = cl;
    }
}

// ---------------- host glue ----------------
typedef CUresult (*EncodeFn)(CUtensorMap*, CUtensorMapDataType, cuuint32_t, void*,
                             const cuuint64_t*, const cuuint64_t*, const cuuint32_t*,
                             const cuuint32_t*, CUtensorMapInterleave, CUtensorMapSwizzle,
                             CUtensorMapL2promotion, CUtensorMapFloatOOBfill);

static void make2d(EncodeFn enc, CUtensorMap* m, void* ptr, uint64_t dimx, uint64_t dimy,
                   uint32_t boxy) {
    cuuint64_t dims[2] = {dimx, dimy};
    cuuint64_t strides[1] = {dimx * 4};
    cuuint32_t box[2] = {32, boxy};
    cuuint32_t es[2] = {1, 1};
    enc(m, CU_TENSOR_MAP_DATA_TYPE_FLOAT32, 2, ptr, dims, strides, box, es,
        CU_TENSOR_MAP_INTERLEAVE_NONE, CU_TENSOR_MAP_SWIZZLE_128B,
        CU_TENSOR_MAP_L2_PROMOTION_L2_128B, CU_TENSOR_MAP_FLOAT_OOB_FILL_NONE);
}

extern "C" void kernel_launch(void* const* d_in, const int* in_sizes, int n_in,
                              void* d_out, int out_size) {
    const float* x   = (const float*)d_in[0];
    const float* w0f = (const float*)d_in[1];
    const float* b0f = (const float*)d_in[2];
    const float* w0r = (const float*)d_in[3];
    const float* b0r = (const float*)d_in[4];
    const float* w1f = (const float*)d_in[5];
    const float* b1f = (const float*)d_in[6];
    const float* w1r = (const float*)d_in[7];
    const float* b1r = (const float*)d_in[8];
    float* out = (float*)d_out;

    void* p;
    cudaGetSymbolAddress(&p, g_xp0);   float* xp0   = (float*)p;
    cudaGetSymbolAddress(&p, g_xp1);   float* xp1   = (float*)p;
    cudaGetSymbolAddress(&p, g_gates); float* gates = (float*)p;
    cudaGetSymbolAddress(&p, g_wt0);   float* wt0   = (float*)p;
    cudaGetSymbolAddress(&p, g_wt1);   float* wt1   = (float*)p;

    void* pfn = nullptr;
    cudaDriverEntryPointQueryResult qres;
    cudaGetDriverEntryPoint("cuTensorMapEncodeTiled", &pfn, cudaEnableDefault, &qres);
    EncodeFn enc = (EncodeFn)pfn;

    CUtensorMap tA0, tB0, tA1, tB1;
    make2d(enc, &tA0, xp0, D0, (uint64_t)BQ * LP, 128);
    make2d(enc, &tB0, wt0, 3 * D0, NG2, 128);
    make2d(enc, &tA1, xp1, D1, (uint64_t)BQ * LP, 128);
    make2d(enc, &tB1, wt1, 3 * D1, NG2, 128);

    const int SMEM_TC = 1024 + 3 * 32768;  // 99328 -> 2 CTAs/SM (smem+TMEM both fit)
    cudaFuncSetAttribute(gemm_tc, cudaFuncAttributeMaxDynamicSharedMemorySize, SMEM_TC);
    cudaFuncSetAttribute(gemm_legacy, cudaFuncAttributeMaxDynamicSharedMemorySize, 65536);

    const size_t OUT2 = (size_t)BQ * LQ * 1024;
    float* h1 = out + OUT2;
    float* h2 = h1 + BQ * 1024;
    float* c1 = h2 + BQ * 1024;
    float* c2 = c1 + BQ * 1024;

    dim3 tgrid(24, 128);   // 24 N-tiles(128), 128 M-pairs(256)
    dim3 lgrid(24, 256);

    // ordering keeps gemm_tc at profiled index 5 (+2 harness launches)
    pad_x_kernel<<<(BQ * LP * D0 + 255) / 256, 256>>>(x);                        // 0
    wtrans_kernel<<<NG2, 256>>>(w0f, w0r, wt0, D0);                              // 1
    gemm_legacy<<<lgrid, 256, 65536>>>(xp0, wt0, b0f, b0r, gates, D0, 9, 48);    // 2 (empty on 103a)
    gemm_tc<<<tgrid, 192, SMEM_TC>>>(tA0, tB0, b0f, b0r, gates, 9, 48);          // 3
    zero_xp1_bounds_kernel<<<(BQ * 2 * D1 + 255) / 256, 256>>>();                // 4
    wtrans_kernel<<<NG2, 256>>>(w1f, w1r, wt1, D1);                              // 5
    scanA_kernel<<<1024, 256>>>(gates);                                          // 6
    scanB_kernel<<<64, 256>>>();                                                 // 7
    scanC_kernel<<<1024, 256>>>(gates, xp1, LP, 1, h1, c1, 1);                   // 8
    gemm_legacy<<<lgrid, 256, 65536>>>(xp1, wt1, b1f, b1r, gates, D1, 10, 96);   // 9 (empty on 103a)
    gemm_tc<<<tgrid, 192, SMEM_TC>>>(tA1, tB1, b1f, b1r, gates, 10, 96);         // 10
    scanA_kernel<<<1024, 256>>>(gates);                                          // 11
    scanB_kernel<<<64, 256>>>();                                                 // 12
    scanC_kernel<<<1024, 256>>>(gates, out, LQ, 0, h2, c2, 0);                   // 13
}

// round 15
// speedup vs baseline: 1.3211x; 1.3211x over previous
#include <cuda_runtime.h>
#include <cuda.h>
#include <cstdint>

#define BQ 16
#define LQ 2048
#define LP 2050
#define OQ 512
#define NG 1536
#define NG2 3072
#define D0 512
#define D1 1024
#define NTILE 12
#define STAGE 49152u

#if defined(__CUDA_ARCH_FEAT_SM103_ALL) || defined(__CUDA_ARCH_FEAT_SM100_ALL)
#define HAS_TCGEN05 1
#else
#define HAS_TCGEN05 0
#endif

// ---------------- device scratch ----------------
static __device__ float g_xp0[(size_t)BQ * LP * D0];
static __device__ float g_xp1[(size_t)BQ * LP * D1];
static __device__ float g_gates[(size_t)BQ * LQ * NG2];
static __device__ float g_wt0[(size_t)NG2 * 3 * D0];
static __device__ float g_wt1[(size_t)NG2 * 3 * D1];
static __device__ float g_P[262144];
static __device__ float g_Q[262144];
static __device__ float g_cin[262144];

__device__ __forceinline__ float tf32r(float v) {
    uint32_t u;
    asm("cvt.rna.tf32.f32 %0, %1;" : "=r"(u) : "f"(v));
    return __uint_as_float(u);
}
__device__ __forceinline__ float sig_f(float x) {
    return __fdividef(1.f, 1.f + __expf(-x));
}
__device__ __forceinline__ float tanh_f(float x) {
    return __fdividef(2.f, 1.f + __expf(-2.f * x)) - 1.f;
}

// ---------------- setup kernels ----------------
__global__ void pad_x_kernel(const float* __restrict__ x) {
    int idx = blockIdx.x * blockDim.x + threadIdx.x;
    if (idx >= BQ * LP * D0) return;
    int b = idx / (LP * D0);
    int rem = idx - b * (LP * D0);
    int tt = rem >> 9;
    int c = rem & 511;
    float v = 0.f;
    if (tt >= 1 && tt <= LQ) v = x[((size_t)b * LQ + (tt - 1)) * D0 + c];
    g_xp0[idx] = tf32r(v);
}

__global__ void zero_xp1_bounds_kernel() {
    int idx = blockIdx.x * blockDim.x + threadIdx.x;
    if (idx >= BQ * 2 * D1) return;
    int b = idx / (2 * D1);
    int r = (idx >> 10) & 1;
    int c = idx & 1023;
    g_xp1[((size_t)b * LP + (r ? (LP - 1) : 0)) * D1 + c] = 0.f;
}

__global__ void __launch_bounds__(256) wtrans_kernel(const float* __restrict__ wf,
                                                     const float* __restrict__ wr,
                                                     float* __restrict__ dst, int Din) {
    __shared__ float smt[3072];
    int row = blockIdx.x;
    int K3 = 3 * Din;
    const float* w = (row < NG) ? wf : wr;
    int oc = (row < NG) ? row : row - NG;
    const float* src = w + (size_t)oc * K3;
    for (int j2 = threadIdx.x; j2 < K3; j2 += 256) {
        int i = j2 / 3;
        int k = j2 - 3 * i;
        smt[k * Din + i] = tf32r(src[j2]);
    }
    __syncthreads();
    float* drow = dst + (size_t)row * K3;
    for (int j = threadIdx.x; j < K3; j += 256) drow[j] = smt[j];
}

// ---------------- ptx helpers ----------------
__device__ __forceinline__ uint32_t elect1() {
    uint32_t p;
    asm volatile("{ .reg .pred p; elect.sync _|p, 0xFFFFFFFF; selp.b32 %0, 1, 0, p; }" : "=r"(p));
    return p;
}
__device__ __forceinline__ void mbar_init(uint32_t a, uint32_t c) {
    asm volatile("mbarrier.init.shared.b64 [%0], %1;" ::"r"(a), "r"(c) : "memory");
}
__device__ __forceinline__ void mbar_arrive(uint32_t a) {
    asm volatile("mbarrier.arrive.shared.b64 _, [%0];" ::"r"(a) : "memory");
}
__device__ __forceinline__ void mbar_expect(uint32_t a, uint32_t b) {
    asm volatile("mbarrier.arrive.expect_tx.shared.b64 _, [%0], %1;" ::"r"(a), "r"(b) : "memory");
}
__device__ __forceinline__ void mbar_wait(uint32_t a, uint32_t ph) {
    asm volatile(
        "{ .reg .pred P; LW_%=: mbarrier.try_wait.parity.acquire.cta.shared::cta.b64 P, [%0], %1, 0x989680;"
        " @P bra LD_%=; bra LW_%=; LD_%=: }" ::"r"(a), "r"(ph) : "memory");
}
__device__ __forceinline__ void mbar_wait_rlx(uint32_t a, uint32_t ph) {
    asm volatile(
        "{ .reg .pred P; LW_%=: mbarrier.try_wait.parity.relaxed.cta.shared::cta.b64 P, [%0], %1, 0x989680;"
        " @P bra LD_%=; bra LW_%=; LD_%=: }" ::"r"(a), "r"(ph) : "memory");
}
__device__ __forceinline__ void tma2d(uint32_t dst, const CUtensorMap* tm, int x, int y, uint32_t mbar) {
    asm volatile(
        "cp.async.bulk.tensor.2d.shared::cta.global.tile.mbarrier::complete_tx::bytes "
        "[%0], [%1, {%2, %3}], [%4];" ::"r"(dst), "l"(tm), "r"(x), "r"(y), "r"(mbar)
        : "memory");
}
__device__ __forceinline__ uint64_t mkdesc(uint32_t addr) {
    // SW128, version=1, SBO=64 (1024B), LBO=1 (16B)
    return 0x4000404000010000ULL | ((uint64_t)(addr >> 4) & 0x3FFF);
}
// tf32 idesc: dtype=F32, a/b=TF32, M=128, N=256
#define IDESC_TF32 0x8400910u

#if HAS_TCGEN05
__device__ __forceinline__ void mma_tf32_tc(uint32_t d, uint64_t ad, uint64_t bd, bool acc) {
    uint32_t en = acc ? 1u : 0u;
    asm volatile(
        "{\n\t.reg .pred p;\n\tsetp.ne.u32 p, %4, 0;\n\t"
        "tcgen05.mma.cta_group::1.kind::tf32 [%0], %1, %2, %3, {%5,%5,%5,%5}, p;\n\t}"
        ::"r"(d), "l"(ad), "l"(bd), "r"(IDESC_TF32), "r"(en), "r"(0u)
        : "memory");
}
#define TALLOC(sa, n) asm volatile("tcgen05.alloc.cta_group::1.sync.aligned.shared::cta.b32 [%0], %1;" ::"r"(sa), "r"(n) : "memory")
#define TDEALLOC(t, n) asm volatile("tcgen05.dealloc.cta_group::1.sync.aligned.b32 %0, %1;" ::"r"(t), "r"(n))
#define TRELINQ() asm volatile("tcgen05.relinquish_alloc_permit.cta_group::1.sync.aligned;")
#define TCOMMIT(a) asm volatile("tcgen05.commit.cta_group::1.mbarrier::arrive::one.shared::cluster.b64 [%0];" ::"r"(a) : "memory")
#define TFENCE_AFTER() asm volatile("tcgen05.fence::after_thread_sync;" ::: "memory")
#define TFENCE_BEFORE() asm volatile("tcgen05.fence::before_thread_sync;" ::: "memory")
#define TWAIT_LD() asm volatile("tcgen05.wait::ld.sync.aligned;" ::: "memory")
#define TLD_X32(r, a)                                                                           \
    asm volatile(                                                                               \
        "tcgen05.ld.sync.aligned.32x32b.x32.b32 "                                               \
        "{%0, %1, %2, %3, %4, %5, %6, %7, %8, %9, %10, %11, %12, %13, %14, %15, "               \
        " %16, %17, %18, %19, %20, %21, %22, %23, %24, %25, %26, %27, %28, %29, %30, %31}, "    \
        "[%32];"                                                                                \
        : "=r"((r)[0]), "=r"((r)[1]), "=r"((r)[2]), "=r"((r)[3]), "=r"((r)[4]), "=r"((r)[5]),   \
          "=r"((r)[6]), "=r"((r)[7]), "=r"((r)[8]), "=r"((r)[9]), "=r"((r)[10]), "=r"((r)[11]), \
          "=r"((r)[12]), "=r"((r)[13]), "=r"((r)[14]), "=r"((r)[15]), "=r"((r)[16]),            \
          "=r"((r)[17]), "=r"((r)[18]), "=r"((r)[19]), "=r"((r)[20]), "=r"((r)[21]),            \
          "=r"((r)[22]), "=r"((r)[23]), "=r"((r)[24]), "=r"((r)[25]), "=r"((r)[26]),            \
          "=r"((r)[27]), "=r"((r)[28]), "=r"((r)[29]), "=r"((r)[30]), "=r"((r)[31])             \
        : "r"(a))
#endif

// =====================================================================
// PATH A: persistent tcgen05 tf32 GEMM with TMEM double buffering.
// Tile M=128 x N=256 (256 TMEM cols), 2 tile buffers in 512-col alloc.
// Epilogue of tile i overlaps mainloop of tile i+1. 148 persistent CTAs.
// Stage = A 16K + B 32K (SW128, K-tile 32) x 3 stages.
// =====================================================================
__global__ void __launch_bounds__(320, 1) gemm_tc(
    const __grid_constant__ CUtensorMap dA,
    const __grid_constant__ CUtensorMap dB,
    const float* __restrict__ bf, const float* __restrict__ br,
    float* __restrict__ G, int DinLog, int numKt, int numTiles) {
#if HAS_TCGEN05
    extern __shared__ char smem[];
    uint32_t sb = (uint32_t)__cvta_generic_to_shared(smem);
    const uint32_t TMEMP = sb;
    const uint32_t BARB = sb + 16;    // full[s]=+s*16, empty[s]=+s*16+8
    const uint32_t DONE = sb + 64;    // done[buf] = +buf*8
    const uint32_t EFREE = sb + 80;   // efree[buf] = +buf*8
    const uint32_t SA = sb + 1024;    // stage: A 16K | B 32K

    int tid = threadIdx.x, lane = tid & 31, wid = tid >> 5;
    int Din = 1 << DinLog;

    if (tid == 0) {
        for (int s = 0; s < 3; s++) {
            mbar_init(BARB + s * 16, 1);
            mbar_init(BARB + s * 16 + 8, 1);
        }
        mbar_init(DONE, 1);
        mbar_init(DONE + 8, 1);
        mbar_init(EFREE, 1);
        mbar_init(EFREE + 8, 1);
    }
    if (wid == 9) TALLOC(TMEMP, 512);
    __syncthreads();
    uint32_t tmem;
    asm volatile("ld.shared.b32 %0, [%1];" : "=r"(tmem) : "r"(TMEMP));

    if (wid == 8) {                       // TMA producer: continuous stage ring
        if (elect1()) {
            int ph = 1, s = 0;
            for (int t = blockIdx.x; t < numTiles; t += gridDim.x) {
                int m0 = (t / NTILE) << 7;
                int n0 = (t % NTILE) << 8;
                int Rbase = (m0 >> 11) * LP + (m0 & 2047);
                for (int kt = 0; kt < numKt; kt++) {
                    mbar_wait_rlx(BARB + s * 16 + 8, ph);
                    mbar_expect(BARB + s * 16, STAGE);
                    int j0 = kt << 5;
                    int q = j0 >> DinLog, r = j0 & (Din - 1);
                    uint32_t st = SA + s * STAGE;
                    tma2d(st, &dA, r, Rbase + q, BARB + s * 16);
                    tma2d(st + 16384u, &dB, j0, n0, BARB + s * 16);
                    if (++s == 3) { s = 0; ph ^= 1; }
                }
            }
        }
    } else if (wid == 9) {                // MMA issuer with tile double-buffer
        if (elect1()) {
            int phF = 0, s = 0;
            int phE0 = 1, phE1 = 1;
            int i = 0;
            for (int t = blockIdx.x; t < numTiles; t += gridDim.x, i++) {
                int buf = i & 1;
                if (buf == 0) { mbar_wait_rlx(EFREE, phE0); phE0 ^= 1; }
                else          { mbar_wait_rlx(EFREE + 8, phE1); phE1 ^= 1; }
                TFENCE_AFTER();
                uint32_t dbase = tmem + buf * 256;
                for (int kt = 0; kt < numKt; kt++) {
                    mbar_wait_rlx(BARB + s * 16, phF);
                    uint32_t st = SA + s * STAGE;
                    uint64_t ad = mkdesc(st);
                    uint64_t bd = mkdesc(st + 16384u);
#pragma unroll
                    for (int ks = 0; ks < 4; ks++) {
                        bool acc = (kt | ks) != 0;
                        mma_tf32_tc(dbase, ad + ks * 2, bd + ks * 2, acc);
                    }
                    TCOMMIT(BARB + s * 16 + 8);
                    if (++s == 3) { s = 0; phF ^= 1; }
                }
                TCOMMIT(DONE + buf * 8);
            }
        }
    }

    if (wid < 8) {                        // epilogue: drain prev tile's buffer
        int phD0 = 0, phD1 = 0;
        int nhalf = wid >> 2;
        int i = 0;
        for (int t = blockIdx.x; t < numTiles; t += gridDim.x, i++) {
            int buf = i & 1;
            if (buf == 0) { mbar_wait(DONE, phD0); phD0 ^= 1; }
            else          { mbar_wait(DONE + 8, phD1); phD1 ^= 1; }
            TFENCE_AFTER();
            int m0 = (t / NTILE) << 7;
            int n0 = (t % NTILE) << 8;
            int mrow = m0 + (wid & 3) * 32 + lane;
            float* grow = G + (size_t)mrow * NG2;
#pragma unroll 1
            for (int cb = 0; cb < 4; cb++) {
                uint32_t r[32];
                TLD_X32(r, tmem + buf * 256 + nhalf * 128 + cb * 32);
                TWAIT_LD();
                int nb = n0 + nhalf * 128 + cb * 32;
                int cmod = (nb >= NG) ? nb - NG : nb;
                const float* bias = (nb >= NG) ? (br + cmod) : (bf + cmod);
                bool ist = cmod >= 2 * OQ;
#pragma unroll
                for (int j = 0; j < 32; j += 4) {
                    float v0 = __uint_as_float(r[j + 0]) + bias[j + 0];
                    float v1 = __uint_as_float(r[j + 1]) + bias[j + 1];
                    float v2 = __uint_as_float(r[j + 2]) + bias[j + 2];
                    float v3 = __uint_as_float(r[j + 3]) + bias[j + 3];
                    float4 o4;
                    o4.x = ist ? tanh_f(v0) : sig_f(v0);
                    o4.y = ist ? tanh_f(v1) : sig_f(v1);
                    o4.z = ist ? tanh_f(v2) : sig_f(v2);
                    o4.w = ist ? tanh_f(v3) : sig_f(v3);
                    *(float4*)(grow + nb + j) = o4;
                }
            }
            TFENCE_BEFORE();
            asm volatile("bar.sync 1, 256;" ::: "memory");
            if (tid == 0) mbar_arrive(EFREE + buf * 8);
        }
    }
    __syncthreads();
    if (wid == 9) {
        TRELINQ();
        TDEALLOC(tmem, 512);
    }
#endif  // HAS_TCGEN05
}

// =====================================================================
// PATH B: legacy mma.sync tf32 GEMM (fallback when no 103a PTX)
// =====================================================================
__device__ __forceinline__ void mma_tf32_leg(float* d, const uint32_t* a, const uint32_t* b) {
    asm volatile(
        "mma.sync.aligned.m16n8k8.row.col.f32.tf32.tf32.f32 "
        "{%0,%1,%2,%3}, {%4,%5,%6,%7}, {%8,%9}, {%0,%1,%2,%3};"
        : "+f"(d[0]), "+f"(d[1]), "+f"(d[2]), "+f"(d[3])
        : "r"(a[0]), "r"(a[1]), "r"(a[2]), "r"(a[3]), "r"(b[0]), "r"(b[1]));
}

__global__ void __launch_bounds__(256, 2) gemm_legacy(
    const float* __restrict__ A, const float* __restrict__ W,
    const float* __restrict__ bf, const float* __restrict__ br,
    float* __restrict__ G, int Din, int DinLog, int numKt) {
#if !HAS_TCGEN05
    extern __shared__ float sm[];
    const int K3 = Din * 3;
    int tid = threadIdx.x, lane = tid & 31, warp = tid >> 5;
    int wm = warp >> 2, wn = warp & 3;
    int m0 = blockIdx.y << 7, n0 = blockIdx.x << 7;
    int bb = m0 >> 11, t0 = m0 & 2047;
    size_t Rbase = (size_t)bb * LP + t0;
    uint32_t sbase = (uint32_t)__cvta_generic_to_shared(sm);

    float acc[4][4][4];
#pragma unroll
    for (int i = 0; i < 4; i++)
#pragma unroll
        for (int j = 0; j < 4; j++)
#pragma unroll
            for (int k = 0; k < 4; k++) acc[i][j][k] = 0.f;

    auto load_tiles = [&](int s, int kt) {
        int j0 = kt << 5;
        int q = j0 >> DinLog, r = j0 & (Din - 1);
        const float* Ab = A + (Rbase + q) * (size_t)Din + r;
        const float* Bb = W + j0;
        uint32_t aoff = sbase + s * 16384u;
        uint32_t boff = sbase + 32768u + s * 16384u;
#pragma unroll
        for (int u = 0; u < 4; u++) {
            int idx2 = (u << 8) + tid;
            int row = idx2 >> 3, g4 = idx2 & 7;
            uint32_t d = (uint32_t)((row << 5) + ((g4 ^ (row & 7)) << 2)) * 4u;
            const float* sa = Ab + (size_t)row * Din + (g4 << 2);
            const float* sb2 = Bb + (size_t)(n0 + row) * K3 + (g4 << 2);
            asm volatile("cp.async.cg.shared.global [%0], [%1], 16;" ::"r"(aoff + d), "l"(sa));
            asm volatile("cp.async.cg.shared.global [%0], [%1], 16;" ::"r"(boff + d), "l"(sb2));
        }
    };

    load_tiles(0, 0);
    asm volatile("cp.async.commit_group;");
    int r4 = lane >> 2, c4 = lane & 3;

    for (int kt = 0; kt < numKt; kt++) {
        int cur = kt & 1;
        if (kt + 1 < numKt) {
            load_tiles(cur ^ 1, kt + 1);
            asm volatile("cp.async.commit_group;");
            asm volatile("cp.async.wait_group 1;");
        } else {
            asm volatile("cp.async.wait_group 0;");
        }
        __syncthreads();
        const float* As_ = sm + cur * 4096;
        const float* Bs_ = sm + 8192 + cur * 4096;
#pragma unroll
        for (int kk = 0; kk < 4; kk++) {
            int g0 = ((2 * kk) ^ r4) << 2, g1 = ((2 * kk + 1) ^ r4) << 2;
            uint32_t a[4][4], bq[4][2];
#pragma unroll
            for (int mi = 0; mi < 4; mi++) {
                int row = (wm << 6) + (mi << 4) + r4;
                a[mi][0] = __float_as_uint(As_[(row << 5) + g0 + c4]);
                a[mi][1] = __float_as_uint(As_[((row + 8) << 5) + g0 + c4]);
                a[mi][2] = __float_as_uint(As_[(row << 5) + g1 + c4]);
                a[mi][3] = __float_as_uint(As_[((row + 8) << 5) + g1 + c4]);
            }
#pragma unroll
            for (int ni = 0; ni < 4; ni++) {
                int row = (wn << 5) + (ni << 3) + r4;
                bq[ni][0] = __float_as_uint(Bs_[(row << 5) + g0 + c4]);
                bq[ni][1] = __float_as_uint(Bs_[(row << 5) + g1 + c4]);
            }
#pragma unroll
            for (int mi = 0; mi < 4; mi++)
#pragma unroll
                for (int ni = 0; ni < 4; ni++) mma_tf32_leg(acc[mi][ni], a[mi], bq[ni]);
        }
        __syncthreads();
    }

#pragma unroll
    for (int mi = 0; mi < 4; mi++) {
        int mrow = m0 + (wm << 6) + (mi << 4) + r4;
#pragma unroll
        for (int ni = 0; ni < 4; ni++) {
            int n = n0 + (wn << 5) + (ni << 3) + (c4 << 1);
            int cmod = (n >= NG) ? n - NG : n;
            float bias0 = (n >= NG) ? br[n - NG] : bf[n];
            float bias1 = (n >= NG) ? br[n - NG + 1] : bf[n + 1];
            float v0 = acc[mi][ni][0] + bias0;
            float v1 = acc[mi][ni][1] + bias1;
            float v2 = acc[mi][ni][2] + bias0;
            float v3 = acc[mi][ni][3] + bias1;
            bool is_tanh = (cmod >= 2 * OQ);
            float a0 = is_tanh ? tanh_f(v0) : sig_f(v0);
            float a1 = is_tanh ? tanh_f(v1) : sig_f(v1);
            float a2 = is_tanh ? tanh_f(v2) : sig_f(v2);
            float a3 = is_tanh ? tanh_f(v3) : sig_f(v3);
            *(float2*)(G + (size_t)mrow * NG2 + n) = make_float2(a0, a1);
            *(float2*)(G + (size_t)(mrow + 8) * NG2 + n) = make_float2(a2, a3);
        }
    }
#endif  // !HAS_TCGEN05
}

// ---------------- 3-phase fo-pool scan (16x parallelism) ----------------
__global__ void __launch_bounds__(256) scanA_kernel(const float* __restrict__ Gt) {
    int idx = blockIdx.x * 256 + threadIdx.x;
    int chain = idx & 16383;
    int q = idx >> 14;
    int dir = chain >> 13, b = (chain >> 9) & 15, ch = chain & 511;
    const float* g = Gt + (size_t)b * LQ * NG2 + dir * NG + ch;
    float c = 0.f, Pp = 1.f;
    int s0 = q << 7;
    for (int su = 0; su < 128; su += 8) {
        float fv[8], zv[8];
#pragma unroll
        for (int u = 0; u < 8; u++) {
            int s = s0 + su + u;
            int t = dir ? (LQ - 1 - s) : s;
            size_t o = (size_t)t * NG2;
            fv[u] = g[o];
            zv[u] = g[o + 1024];
        }
#pragma unroll
        for (int u = 0; u < 8; u++) {
            Pp *= fv[u];
            c = fv[u] * (c - zv[u]) + zv[u];
        }
    }
    g_P[idx] = Pp;
    g_Q[idx] = c;
}

__global__ void __launch_bounds__(256) scanB_kernel() {
    int chain = blockIdx.x * 256 + threadIdx.x;
    float c = 0.f;
#pragma unroll
    for (int q = 0; q < 16; q++) {
        int id = (q << 14) + chain;
        g_cin[id] = c;
        c = g_P[id] * c + g_Q[id];
    }
}

__global__ void __launch_bounds__(256) scanC_kernel(
    const float* __restrict__ Gt, float* __restrict__ dst, int rowsPerB, int tOff,
    float* __restrict__ hdst, float* __restrict__ cdst, int doRound) {
    int idx = blockIdx.x * 256 + threadIdx.x;
    int chain = idx & 16383;
    int q = idx >> 14;
    int dir = chain >> 13, b = (chain >> 9) & 15, ch = chain & 511;
    const float* g = Gt + (size_t)b * LQ * NG2 + dir * NG + ch;
    int cc = (dir << 9) + ch;
    float* d = dst + ((size_t)b * rowsPerB + tOff) * 1024 + cc;
    float c = g_cin[idx];
    float hl = 0.f, cl = 0.f;
    int s0 = q << 7;
    for (int su = 0; su < 128; su += 8) {
        float fv[8], ov[8], zv[8];
#pragma unroll
        for (int u = 0; u < 8; u++) {
            int s = s0 + su + u;
            int t = dir ? (LQ - 1 - s) : s;
            size_t o = (size_t)t * NG2;
            fv[u] = g[o];
            ov[u] = g[o + 512];
            zv[u] = g[o + 1024];
        }
#pragma unroll
        for (int u = 0; u < 8; u++) {
            int s = s0 + su + u;
            int t = dir ? (LQ - 1 - s) : s;
            c = fv[u] * (c - zv[u]) + zv[u];
            float h = c * ov[u];
            d[(size_t)t * 1024] = doRound ? tf32r(h) : h;
            if ((dir == 0 && s == LQ - 1) || (dir == 1 && s == 0)) { hl = h; cl = c; }
        }
    }
    if ((dir == 0 && q == 15) || (dir == 1 && q == 0)) {
        hdst[b * 1024 + cc] = hl;
        cdst[b * 1024 + cc] = cl;
    }
}

// ---------------- host glue ----------------
typedef CUresult (*EncodeFn)(CUtensorMap*, CUtensorMapDataType, cuuint32_t, void*,
                             const cuuint64_t*, const cuuint64_t*, const cuuint32_t*,
                             const cuuint32_t*, CUtensorMapInterleave, CUtensorMapSwizzle,
                             CUtensorMapL2promotion, CUtensorMapFloatOOBfill);

static void make2d(EncodeFn enc, CUtensorMap* m, void* ptr, uint64_t dimx, uint64_t dimy,
                   uint32_t boxy) {
    cuuint64_t dims[2] = {dimx, dimy};
    cuuint64_t strides[1] = {dimx * 4};
    cuuint32_t box[2] = {32, boxy};
    cuuint32_t es[2] = {1, 1};
    enc(m, CU_TENSOR_MAP_DATA_TYPE_FLOAT32, 2, ptr, dims, strides, box, es,
        CU_TENSOR_MAP_INTERLEAVE_NONE, CU_TENSOR_MAP_SWIZZLE_128B,
        CU_TENSOR_MAP_L2_PROMOTION_L2_128B, CU_TENSOR_MAP_FLOAT_OOB_FILL_NONE);
}

extern "C" void kernel_launch(void* const* d_in, const int* in_sizes, int n_in,
                              void* d_out, int out_size) {
    const float* x   = (const float*)d_in[0];
    const float* w0f = (const float*)d_in[1];
    const float* b0f = (const float*)d_in[2];
    const float* w0r = (const float*)d_in[3];
    const float* b0r = (const float*)d_in[4];
    const float* w1f = (const float*)d_in[5];
    const float* b1f = (const float*)d_in[6];
    const float* w1r = (const float*)d_in[7];
    const float* b1r = (const float*)d_in[8];
    float* out = (float*)d_out;

    void* p;
    cudaGetSymbolAddress(&p, g_xp0);   float* xp0   = (float*)p;
    cudaGetSymbolAddress(&p, g_xp1);   float* xp1   = (float*)p;
    cudaGetSymbolAddress(&p, g_gates); float* gates = (float*)p;
    cudaGetSymbolAddress(&p, g_wt0);   float* wt0   = (float*)p;
    cudaGetSymbolAddress(&p, g_wt1);   float* wt1   = (float*)p;

    void* pfn = nullptr;
    cudaDriverEntryPointQueryResult qres;
    cudaGetDriverEntryPoint("cuTensorMapEncodeTiled", &pfn, cudaEnableDefault, &qres);
    EncodeFn enc = (EncodeFn)pfn;

    CUtensorMap tA0, tB0, tA1, tB1;
    make2d(enc, &tA0, xp0, D0, (uint64_t)BQ * LP, 128);   // A box [32,128]
    make2d(enc, &tB0, wt0, 3 * D0, NG2, 256);             // B box [32,256]
    make2d(enc, &tA1, xp1, D1, (uint64_t)BQ * LP, 128);
    make2d(enc, &tB1, wt1, 3 * D1, NG2, 256);

    const int SMEM_TC = 1024 + 3 * (int)STAGE;  // 148480
    cudaFuncSetAttribute(gemm_tc, cudaFuncAttributeMaxDynamicSharedMemorySize, SMEM_TC);
    cudaFuncSetAttribute(gemm_legacy, cudaFuncAttributeMaxDynamicSharedMemorySize, 65536);

    const size_t OUT2 = (size_t)BQ * LQ * 1024;
    float* h1 = out + OUT2;
    float* h2 = h1 + BQ * 1024;
    float* c1 = h2 + BQ * 1024;
    float* c2 = c1 + BQ * 1024;

    const int NT = NTILE * 256;   // 3072 tiles (256 M-tiles x 12 N-tiles)
    dim3 lgrid(24, 256);

    // ordering keeps gemm_tc at profiled index 5 (+2 harness launches)
    pad_x_kernel<<<(BQ * LP * D0 + 255) / 256, 256>>>(x);                        // 0
    wtrans_kernel<<<NG2, 256>>>(w0f, w0r, wt0, D0);                              // 1
    gemm_legacy<<<lgrid, 256, 65536>>>(xp0, wt0, b0f, b0r, gates, D0, 9, 48);    // 2 (empty on 103a)
    gemm_tc<<<148, 320, SMEM_TC>>>(tA0, tB0, b0f, b0r, gates, 9, 48, NT);        // 3
    zero_xp1_bounds_kernel<<<(BQ * 2 * D1 + 255) / 256, 256>>>();                // 4
    wtrans_kernel<<<NG2, 256>>>(w1f, w1r, wt1, D1);                              // 5
    scanA_kernel<<<1024, 256>>>(gates);                                          // 6
    scanB_kernel<<<64, 256>>>();                                                 // 7
    scanC_kernel<<<1024, 256>>>(gates, xp1, LP, 1, h1, c1, 1);                   // 8
    gemm_legacy<<<lgrid, 256, 65536>>>(xp1, wt1, b1f, b1r, gates, D1, 10, 96);   // 9 (empty on 103a)
    gemm_tc<<<148, 320, SMEM_TC>>>(tA1, tB1, b1f, b1r, gates, 10, 96, NT);       // 10
    scanA_kernel<<<1024, 256>>>(gates);                                          // 11
    scanB_kernel<<<64, 256>>>();                                                 // 12
    scanC_kernel<<<1024, 256>>>(gates, out, LQ, 0, h2, c2, 0);                   // 13
}

// round 16
// speedup vs baseline: 1.3731x; 1.0394x over previous
#include <cuda_runtime.h>
#include <cuda.h>
#include <cstdint>

#define BQ 16
#define LQ 2048
#define LP 2050
#define OQ 512
#define NG 1536
#define NG2 3072
#define D0 512
#define D1 1024
#define NTILE 12
#define STAGE 49152u

#if defined(__CUDA_ARCH_FEAT_SM103_ALL) || defined(__CUDA_ARCH_FEAT_SM100_ALL)
#define HAS_TCGEN05 1
#else
#define HAS_TCGEN05 0
#endif

// ---------------- device scratch ----------------
static __device__ float g_xp0[(size_t)BQ * LP * D0];
static __device__ float g_xp1[(size_t)BQ * LP * D1];
static __device__ float g_gates[(size_t)BQ * LQ * NG2];
static __device__ float g_wt0[(size_t)NG2 * 3 * D0];
static __device__ float g_wt1[(size_t)NG2 * 3 * D1];
static __device__ float g_P[262144];
static __device__ float g_Q[262144];
static __device__ float g_cin[262144];

__device__ __forceinline__ float tf32r(float v) {
    uint32_t u;
    asm("cvt.rna.tf32.f32 %0, %1;" : "=r"(u) : "f"(v));
    return __uint_as_float(u);
}
__device__ __forceinline__ float sig_f(float x) {
    return __fdividef(1.f, 1.f + __expf(-x));
}
__device__ __forceinline__ float tanh_f(float x) {
    return __fdividef(2.f, 1.f + __expf(-2.f * x)) - 1.f;
}

// ---------------- setup kernels ----------------
__global__ void pad_x_kernel(const float* __restrict__ x) {
    int idx = blockIdx.x * blockDim.x + threadIdx.x;
    if (idx >= BQ * LP * D0) return;
    int b = idx / (LP * D0);
    int rem = idx - b * (LP * D0);
    int tt = rem >> 9;
    int c = rem & 511;
    float v = 0.f;
    if (tt >= 1 && tt <= LQ) v = x[((size_t)b * LQ + (tt - 1)) * D0 + c];
    g_xp0[idx] = tf32r(v);
}

__global__ void zero_xp1_bounds_kernel() {
    int idx = blockIdx.x * blockDim.x + threadIdx.x;
    if (idx >= BQ * 2 * D1) return;
    int b = idx / (2 * D1);
    int r = (idx >> 10) & 1;
    int c = idx & 1023;
    g_xp1[((size_t)b * LP + (r ? (LP - 1) : 0)) * D1 + c] = 0.f;
}

__global__ void __launch_bounds__(256) wtrans_kernel(const float* __restrict__ wf,
                                                     const float* __restrict__ wr,
                                                     float* __restrict__ dst, int Din) {
    __shared__ float smt[3072];
    int row = blockIdx.x;
    int K3 = 3 * Din;
    const float* w = (row < NG) ? wf : wr;
    int oc = (row < NG) ? row : row - NG;
    const float* src = w + (size_t)oc * K3;
    for (int j2 = threadIdx.x; j2 < K3; j2 += 256) {
        int i = j2 / 3;
        int k = j2 - 3 * i;
        smt[k * Din + i] = tf32r(src[j2]);
    }
    __syncthreads();
    float* drow = dst + (size_t)row * K3;
    for (int j = threadIdx.x; j < K3; j += 256) drow[j] = smt[j];
}

// ---------------- ptx helpers ----------------
__device__ __forceinline__ uint32_t elect1() {
    uint32_t p;
    asm volatile("{ .reg .pred p; elect.sync _|p, 0xFFFFFFFF; selp.b32 %0, 1, 0, p; }" : "=r"(p));
    return p;
}
__device__ __forceinline__ uint32_t ctarank() {
    uint32_t r;
    asm("mov.u32 %0, %%cluster_ctarank;" : "=r"(r));
    return r;
}
__device__ __forceinline__ void mbar_init(uint32_t a, uint32_t c) {
    asm volatile("mbarrier.init.shared.b64 [%0], %1;" ::"r"(a), "r"(c) : "memory");
}
__device__ __forceinline__ void mbar_arrive(uint32_t a) {
    asm volatile("mbarrier.arrive.shared.b64 _, [%0];" ::"r"(a) : "memory");
}
__device__ __forceinline__ void mbar_expect(uint32_t a, uint32_t b) {
    asm volatile("mbarrier.arrive.expect_tx.shared.b64 _, [%0], %1;" ::"r"(a), "r"(b) : "memory");
}
__device__ __forceinline__ void mbar_wait(uint32_t a, uint32_t ph) {
    asm volatile(
        "{ .reg .pred P; LW_%=: mbarrier.try_wait.parity.acquire.cta.shared::cta.b64 P, [%0], %1, 0x989680;"
        " @P bra LD_%=; bra LW_%=; LD_%=: }" ::"r"(a), "r"(ph) : "memory");
}
__device__ __forceinline__ void mbar_wait_rlx(uint32_t a, uint32_t ph) {
    asm volatile(
        "{ .reg .pred P; LW_%=: mbarrier.try_wait.parity.relaxed.cta.shared::cta.b64 P, [%0], %1, 0x989680;"
        " @P bra LD_%=; bra LW_%=; LD_%=: }" ::"r"(a), "r"(ph) : "memory");
}
__device__ __forceinline__ void tma2d(uint32_t dst, const CUtensorMap* tm, int x, int y, uint32_t mbar) {
    asm volatile(
        "cp.async.bulk.tensor.2d.shared::cta.global.tile.mbarrier::complete_tx::bytes "
        "[%0], [%1, {%2, %3}], [%4];" ::"r"(dst), "l"(tm), "r"(x), "r"(y), "r"(mbar)
        : "memory");
}
__device__ __forceinline__ uint64_t mkdesc(uint32_t addr) {
    // SW128, version=1, SBO=64 (1024B), LBO=1 (16B)
    return 0x4000404000010000ULL | ((uint64_t)(addr >> 4) & 0x3FFF);
}
// tf32 idesc: dtype=F32, a/b=TF32, M=128, N=256
#define IDESC_TF32 0x8400910u
#define CLUSTER_SYNC_()                                                 \
    do {                                                                \
        asm volatile("barrier.cluster.arrive.aligned;" ::: "memory");   \
        asm volatile("barrier.cluster.wait.aligned;" ::: "memory");     \
    } while (0)

#if HAS_TCGEN05
__device__ __forceinline__ void tma2d_mc(uint32_t dst, const CUtensorMap* tm, int x, int y,
                                         uint32_t mbar, uint16_t mask) {
    asm volatile(
        "cp.async.bulk.tensor.2d.shared::cluster.global.tile.mbarrier::complete_tx::bytes.multicast::cluster "
        "[%0], [%1, {%2, %3}], [%4], %5;" ::"r"(dst), "l"(tm), "r"(x), "r"(y), "r"(mbar), "h"(mask)
        : "memory");
}
__device__ __forceinline__ void mma_tf32_tc(uint32_t d, uint64_t ad, uint64_t bd, bool acc) {
    uint32_t en = acc ? 1u : 0u;
    asm volatile(
        "{\n\t.reg .pred p;\n\tsetp.ne.u32 p, %4, 0;\n\t"
        "tcgen05.mma.cta_group::1.kind::tf32 [%0], %1, %2, %3, {%5,%5,%5,%5}, p;\n\t}"
        ::"r"(d), "l"(ad), "l"(bd), "r"(IDESC_TF32), "r"(en), "r"(0u)
        : "memory");
}
#define TALLOC(sa, n) asm volatile("tcgen05.alloc.cta_group::1.sync.aligned.shared::cta.b32 [%0], %1;" ::"r"(sa), "r"(n) : "memory")
#define TDEALLOC(t, n) asm volatile("tcgen05.dealloc.cta_group::1.sync.aligned.b32 %0, %1;" ::"r"(t), "r"(n))
#define TRELINQ() asm volatile("tcgen05.relinquish_alloc_permit.cta_group::1.sync.aligned;")
#define TCOMMIT(a) asm volatile("tcgen05.commit.cta_group::1.mbarrier::arrive::one.shared::cluster.b64 [%0];" ::"r"(a) : "memory")
#define TCOMMIT_MC(a, m) asm volatile("tcgen05.commit.cta_group::1.mbarrier::arrive::one.shared::cluster.multicast::cluster.b64 [%0], %1;" ::"r"(a), "h"((uint16_t)(m)) : "memory")
#define TFENCE_AFTER() asm volatile("tcgen05.fence::after_thread_sync;" ::: "memory")
#define TFENCE_BEFORE() asm volatile("tcgen05.fence::before_thread_sync;" ::: "memory")
#define TWAIT_LD() asm volatile("tcgen05.wait::ld.sync.aligned;" ::: "memory")
#define TLD_X32(r, a)                                                                           \
    asm volatile(                                                                               \
        "tcgen05.ld.sync.aligned.32x32b.x32.b32 "                                               \
        "{%0, %1, %2, %3, %4, %5, %6, %7, %8, %9, %10, %11, %12, %13, %14, %15, "               \
        " %16, %17, %18, %19, %20, %21, %22, %23, %24, %25, %26, %27, %28, %29, %30, %31}, "    \
        "[%32];"                                                                                \
        : "=r"((r)[0]), "=r"((r)[1]), "=r"((r)[2]), "=r"((r)[3]), "=r"((r)[4]), "=r"((r)[5]),   \
          "=r"((r)[6]), "=r"((r)[7]), "=r"((r)[8]), "=r"((r)[9]), "=r"((r)[10]), "=r"((r)[11]), \
          "=r"((r)[12]), "=r"((r)[13]), "=r"((r)[14]), "=r"((r)[15]), "=r"((r)[16]),            \
          "=r"((r)[17]), "=r"((r)[18]), "=r"((r)[19]), "=r"((r)[20]), "=r"((r)[21]),            \
          "=r"((r)[22]), "=r"((r)[23]), "=r"((r)[24]), "=r"((r)[25]), "=r"((r)[26]),            \
          "=r"((r)[27]), "=r"((r)[28]), "=r"((r)[29]), "=r"((r)[30]), "=r"((r)[31])             \
        : "r"(a))
#endif

// =====================================================================
// PATH A: persistent tcgen05 tf32 GEMM, TMEM double-buffered epilogue,
// cluster(2,1,1): pair shares B via cooperative TMA multicast slices.
// Pair-tile: rank r does (m0 + r*128, n0); B halves multicast to both.
// Tile M=128 x N=256, K-tile 32 (SW128). Stage = A16K + B32K, x3.
// =====================================================================
__global__ void __launch_bounds__(320, 1) __cluster_dims__(2, 1, 1) gemm_tc(
    const __grid_constant__ CUtensorMap dA,
    const __grid_constant__ CUtensorMap dB,
    const float* __restrict__ bf, const float* __restrict__ br,
    float* __restrict__ G, int DinLog, int numKt, int numPairs) {
#if HAS_TCGEN05
    extern __shared__ char smem[];
    uint32_t sb = (uint32_t)__cvta_generic_to_shared(smem);
    const uint32_t TMEMP = sb;
    const uint32_t BARB = sb + 16;    // full[s]=+s*16, empty[s]=+s*16+8
    const uint32_t DONE = sb + 64;    // done[buf] = +buf*8
    const uint32_t EFREE = sb + 80;   // efree[buf] = +buf*8
    const uint32_t SA = sb + 1024;    // stage: A 16K | B 32K

    int tid = threadIdx.x, lane = tid & 31, wid = tid >> 5;
    int Din = 1 << DinLog;
    uint32_t rank = ctarank();
    int pair = blockIdx.x >> 1;
    int pstep = gridDim.x >> 1;

    if (tid == 0) {
        for (int s = 0; s < 3; s++) {
            mbar_init(BARB + s * 16, 1);       // full: tx-driven
            mbar_init(BARB + s * 16 + 8, 2);   // empty: commit-MC from both ranks
        }
        mbar_init(DONE, 1);
        mbar_init(DONE + 8, 1);
        mbar_init(EFREE, 1);
        mbar_init(EFREE + 8, 1);
    }
    if (wid == 9) TALLOC(TMEMP, 512);
    __syncthreads();
    CLUSTER_SYNC_();                  // peer mbarriers live before multicast
    uint32_t tmem;
    asm volatile("ld.shared.b32 %0, [%1];" : "=r"(tmem) : "r"(TMEMP));

    if (wid == 8) {                       // TMA producer
        if (elect1()) {
            int ph = 1, s = 0;
            for (int tp = pair; tp < numPairs; tp += pstep) {
                int m0 = ((tp / NTILE) << 8) + (int)rank * 128;
                int n0 = (tp % NTILE) << 8;
                int Rbase = (m0 >> 11) * LP + (m0 & 2047);
                for (int kt = 0; kt < numKt; kt++) {
                    mbar_wait_rlx(BARB + s * 16 + 8, ph);
                    mbar_expect(BARB + s * 16, STAGE);   // A16K + ownB16K + peerB16K
                    int j0 = kt << 5;
                    int q = j0 >> DinLog, r = j0 & (Din - 1);
                    uint32_t st = SA + s * STAGE;
                    tma2d(st, &dA, r, Rbase + q, BARB + s * 16);
                    tma2d_mc(st + 16384u + rank * 16384u, &dB, j0, n0 + (int)rank * 128,
                             BARB + s * 16, 0x3);
                    if (++s == 3) { s = 0; ph ^= 1; }
                }
            }
        }
    } else if (wid == 9) {                // MMA issuer with tile double-buffer
        if (elect1()) {
            int phF = 0, s = 0;
            int phE0 = 1, phE1 = 1;
            int i = 0;
            for (int tp = pair; tp < numPairs; tp += pstep, i++) {
                int buf = i & 1;
                if (buf == 0) { mbar_wait_rlx(EFREE, phE0); phE0 ^= 1; }
                else          { mbar_wait_rlx(EFREE + 8, phE1); phE1 ^= 1; }
                TFENCE_AFTER();
                uint32_t dbase = tmem + buf * 256;
                for (int kt = 0; kt < numKt; kt++) {
                    mbar_wait_rlx(BARB + s * 16, phF);
                    uint32_t st = SA + s * STAGE;
                    uint64_t ad = mkdesc(st);
                    uint64_t bd = mkdesc(st + 16384u);
#pragma unroll
                    for (int ks = 0; ks < 4; ks++) {
                        bool acc = (kt | ks) != 0;
                        mma_tf32_tc(dbase, ad + ks * 2, bd + ks * 2, acc);
                    }
                    TCOMMIT_MC(BARB + s * 16 + 8, 0x3);   // free stage in BOTH CTAs
                    if (++s == 3) { s = 0; phF ^= 1; }
                }
                TCOMMIT(DONE + buf * 8);
            }
        }
    }

    if (wid < 8) {                        // epilogue: drain prev tile's buffer
        int phD0 = 0, phD1 = 0;
        int nhalf = wid >> 2;
        int i = 0;
        for (int tp = pair; tp < numPairs; tp += pstep, i++) {
            int buf = i & 1;
            if (buf == 0) { mbar_wait(DONE, phD0); phD0 ^= 1; }
            else          { mbar_wait(DONE + 8, phD1); phD1 ^= 1; }
            TFENCE_AFTER();
            int m0 = ((tp / NTILE) << 8) + (int)rank * 128;
            int n0 = (tp % NTILE) << 8;
            int mrow = m0 + (wid & 3) * 32 + lane;
            float* grow = G + (size_t)mrow * NG2;
#pragma unroll 1
            for (int cb = 0; cb < 4; cb++) {
                uint32_t r[32];
                TLD_X32(r, tmem + buf * 256 + nhalf * 128 + cb * 32);
                TWAIT_LD();
                int nb = n0 + nhalf * 128 + cb * 32;
                int cmod = (nb >= NG) ? nb - NG : nb;
                const float* bias = (nb >= NG) ? (br + cmod) : (bf + cmod);
                bool ist = cmod >= 2 * OQ;
#pragma unroll
                for (int j = 0; j < 32; j += 4) {
                    float v0 = __uint_as_float(r[j + 0]) + bias[j + 0];
                    float v1 = __uint_as_float(r[j + 1]) + bias[j + 1];
                    float v2 = __uint_as_float(r[j + 2]) + bias[j + 2];
                    float v3 = __uint_as_float(r[j + 3]) + bias[j + 3];
                    float4 o4;
                    o4.x = ist ? tanh_f(v0) : sig_f(v0);
                    o4.y = ist ? tanh_f(v1) : sig_f(v1);
                    o4.z = ist ? tanh_f(v2) : sig_f(v2);
                    o4.w = ist ? tanh_f(v3) : sig_f(v3);
                    *(float4*)(grow + nb + j) = o4;
                }
            }
            TFENCE_BEFORE();
            asm volatile("bar.sync 1, 256;" ::: "memory");
            if (tid == 0) mbar_arrive(EFREE + buf * 8);
        }
    }
    __syncthreads();
    CLUSTER_SYNC_();                  // no exit while peer multicast in flight
    if (wid == 9) {
        TRELINQ();
        TDEALLOC(tmem, 512);
    }
#endif  // HAS_TCGEN05
}

// =====================================================================
// PATH B: legacy mma.sync tf32 GEMM (fallback when no 103a PTX)
// =====================================================================
__device__ __forceinline__ void mma_tf32_leg(float* d, const uint32_t* a, const uint32_t* b) {
    asm volatile(
        "mma.sync.aligned.m16n8k8.row.col.f32.tf32.tf32.f32 "
        "{%0,%1,%2,%3}, {%4,%5,%6,%7}, {%8,%9}, {%0,%1,%2,%3};"
        : "+f"(d[0]), "+f"(d[1]), "+f"(d[2]), "+f"(d[3])
        : "r"(a[0]), "r"(a[1]), "r"(a[2]), "r"(a[3]), "r"(b[0]), "r"(b[1]));
}

__global__ void __launch_bounds__(256, 2) gemm_legacy(
    const float* __restrict__ A, const float* __restrict__ W,
    const float* __restrict__ bf, const float* __restrict__ br,
    float* __restrict__ G, int Din, int DinLog, int numKt) {
#if !HAS_TCGEN05
    extern __shared__ float sm[];
    const int K3 = Din * 3;
    int tid = threadIdx.x, lane = tid & 31, warp = tid >> 5;
    int wm = warp >> 2, wn = warp & 3;
    int m0 = blockIdx.y << 7, n0 = blockIdx.x << 7;
    int bb = m0 >> 11, t0 = m0 & 2047;
    size_t Rbase = (size_t)bb * LP + t0;
    uint32_t sbase = (uint32_t)__cvta_generic_to_shared(sm);

    float acc[4][4][4];
#pragma unroll
    for (int i = 0; i < 4; i++)
#pragma unroll
        for (int j = 0; j < 4; j++)
#pragma unroll
            for (int k = 0; k < 4; k++) acc[i][j][k] = 0.f;

    auto load_tiles = [&](int s, int kt) {
        int j0 = kt << 5;
        int q = j0 >> DinLog, r = j0 & (Din - 1);
        const float* Ab = A + (Rbase + q) * (size_t)Din + r;
        const float* Bb = W + j0;
        uint32_t aoff = sbase + s * 16384u;
        uint32_t boff = sbase + 32768u + s * 16384u;
#pragma unroll
        for (int u = 0; u < 4; u++) {
            int idx2 = (u << 8) + tid;
            int row = idx2 >> 3, g4 = idx2 & 7;
            uint32_t d = (uint32_t)((row << 5) + ((g4 ^ (row & 7)) << 2)) * 4u;
            const float* sa = Ab + (size_t)row * Din + (g4 << 2);
            const float* sb2 = Bb + (size_t)(n0 + row) * K3 + (g4 << 2);
            asm volatile("cp.async.cg.shared.global [%0], [%1], 16;" ::"r"(aoff + d), "l"(sa));
            asm volatile("cp.async.cg.shared.global [%0], [%1], 16;" ::"r"(boff + d), "l"(sb2));
        }
    };

    load_tiles(0, 0);
    asm volatile("cp.async.commit_group;");
    int r4 = lane >> 2, c4 = lane & 3;

    for (int kt = 0; kt < numKt; kt++) {
        int cur = kt & 1;
        if (kt + 1 < numKt) {
            load_tiles(cur ^ 1, kt + 1);
            asm volatile("cp.async.commit_group;");
            asm volatile("cp.async.wait_group 1;");
        } else {
            asm volatile("cp.async.wait_group 0;");
        }
        __syncthreads();
        const float* As_ = sm + cur * 4096;
        const float* Bs_ = sm + 8192 + cur * 4096;
#pragma unroll
        for (int kk = 0; kk < 4; kk++) {
            int g0 = ((2 * kk) ^ r4) << 2, g1 = ((2 * kk + 1) ^ r4) << 2;
            uint32_t a[4][4], bq[4][2];
#pragma unroll
            for (int mi = 0; mi < 4; mi++) {
                int row = (wm << 6) + (mi << 4) + r4;
                a[mi][0] = __float_as_uint(As_[(row << 5) + g0 + c4]);
                a[mi][1] = __float_as_uint(As_[((row + 8) << 5) + g0 + c4]);
                a[mi][2] = __float_as_uint(As_[(row << 5) + g1 + c4]);
                a[mi][3] = __float_as_uint(As_[((row + 8) << 5) + g1 + c4]);
            }
#pragma unroll
            for (int ni = 0; ni < 4; ni++) {
                int row = (wn << 5) + (ni << 3) + r4;
                bq[ni][0] = __float_as_uint(Bs_[(row << 5) + g0 + c4]);
                bq[ni][1] = __float_as_uint(Bs_[(row << 5) + g1 + c4]);
            }
#pragma unroll
            for (int mi = 0; mi < 4; mi++)
#pragma unroll
                for (int ni = 0; ni < 4; ni++) mma_tf32_leg(acc[mi][ni], a[mi], bq[ni]);
        }
        __syncthreads();
    }

#pragma unroll
    for (int mi = 0; mi < 4; mi++) {
        int mrow = m0 + (wm << 6) + (mi << 4) + r4;
#pragma unroll
        for (int ni = 0; ni < 4; ni++) {
            int n = n0 + (wn << 5) + (ni << 3) + (c4 << 1);
            int cmod = (n >= NG) ? n - NG : n;
            float bias0 = (n >= NG) ? br[n - NG] : bf[n];
            float bias1 = (n >= NG) ? br[n - NG + 1] : bf[n + 1];
            float v0 = acc[mi][ni][0] + bias0;
            float v1 = acc[mi][ni][1] + bias1;
            float v2 = acc[mi][ni][2] + bias0;
            float v3 = acc[mi][ni][3] + bias1;
            bool is_tanh = (cmod >= 2 * OQ);
            float a0 = is_tanh ? tanh_f(v0) : sig_f(v0);
            float a1 = is_tanh ? tanh_f(v1) : sig_f(v1);
            float a2 = is_tanh ? tanh_f(v2) : sig_f(v2);
            float a3 = is_tanh ? tanh_f(v3) : sig_f(v3);
            *(float2*)(G + (size_t)mrow * NG2 + n) = make_float2(a0, a1);
            *(float2*)(G + (size_t)(mrow + 8) * NG2 + n) = make_float2(a2, a3);
        }
    }
#endif  // !HAS_TCGEN05
}

// ---------------- 3-phase fo-pool scan (16x parallelism) ----------------
__global__ void __launch_bounds__(256) scanA_kernel(const float* __restrict__ Gt) {
    int idx = blockIdx.x * 256 + threadIdx.x;
    int chain = idx & 16383;
    int q = idx >> 14;
    int dir = chain >> 13, b = (chain >> 9) & 15, ch = chain & 511;
    const float* g = Gt + (size_t)b * LQ * NG2 + dir * NG + ch;
    float c = 0.f, Pp = 1.f;
    int s0 = q << 7;
    for (int su = 0; su < 128; su += 8) {
        float fv[8], zv[8];
#pragma unroll
        for (int u = 0; u < 8; u++) {
            int s = s0 + su + u;
            int t = dir ? (LQ - 1 - s) : s;
            size_t o = (size_t)t * NG2;
            fv[u] = g[o];
            zv[u] = g[o + 1024];
        }
#pragma unroll
        for (int u = 0; u < 8; u++) {
            Pp *= fv[u];
            c = fv[u] * (c - zv[u]) + zv[u];
        }
    }
    g_P[idx] = Pp;
    g_Q[idx] = c;
}

__global__ void __launch_bounds__(256) scanB_kernel() {
    int chain = blockIdx.x * 256 + threadIdx.x;
    float c = 0.f;
#pragma unroll
    for (int q = 0; q < 16; q++) {
        int id = (q << 14) + chain;
        g_cin[id] = c;
        c = g_P[id] * c + g_Q[id];
    }
}

__global__ void __launch_bounds__(256) scanC_kernel(
    const float* __restrict__ Gt, float* __restrict__ dst, int rowsPerB, int tOff,
    float* __restrict__ hdst, float* __restrict__ cdst, int doRound) {
    int idx = blockIdx.x * 256 + threadIdx.x;
    int chain = idx & 16383;
    int q = idx >> 14;
    int dir = chain >> 13, b = (chain >> 9) & 15, ch = chain & 511;
    const float* g = Gt + (size_t)b * LQ * NG2 + dir * NG + ch;
    int cc = (dir << 9) + ch;
    float* d = dst + ((size_t)b * rowsPerB + tOff) * 1024 + cc;
    float c = g_cin[idx];
    float hl = 0.f, cl = 0.f;
    int s0 = q << 7;
    for (int su = 0; su < 128; su += 8) {
        float fv[8], ov[8], zv[8];
#pragma unroll
        for (int u = 0; u < 8; u++) {
            int s = s0 + su + u;
            int t = dir ? (LQ - 1 - s) : s;
            size_t o = (size_t)t * NG2;
            fv[u] = g[o];
            ov[u] = g[o + 512];
            zv[u] = g[o + 1024];
        }
#pragma unroll
        for (int u = 0; u < 8; u++) {
            int s = s0 + su + u;
            int t = dir ? (LQ - 1 - s) : s;
            c = fv[u] * (c - zv[u]) + zv[u];
            float h = c * ov[u];
            d[(size_t)t * 1024] = doRound ? tf32r(h) : h;
            if ((dir == 0 && s == LQ - 1) || (dir == 1 && s == 0)) { hl = h; cl = c; }
        }
    }
    if ((dir == 0 && q == 15) || (dir == 1 && q == 0)) {
        hdst[b * 1024 + cc] = hl;
        cdst[b * 1024 + cc] = cl;
    }
}

// ---------------- host glue ----------------
typedef CUresult (*EncodeFn)(CUtensorMap*, CUtensorMapDataType, cuuint32_t, void*,
                             const cuuint64_t*, const cuuint64_t*, const cuuint32_t*,
                             const cuuint32_t*, CUtensorMapInterleave, CUtensorMapSwizzle,
                             CUtensorMapL2promotion, CUtensorMapFloatOOBfill);

static void make2d(EncodeFn enc, CUtensorMap* m, void* ptr, uint64_t dimx, uint64_t dimy,
                   uint32_t boxy) {
    cuuint64_t dims[2] = {dimx, dimy};
    cuuint64_t strides[1] = {dimx * 4};
    cuuint32_t box[2] = {32, boxy};
    cuuint32_t es[2] = {1, 1};
    enc(m, CU_TENSOR_MAP_DATA_TYPE_FLOAT32, 2, ptr, dims, strides, box, es,
        CU_TENSOR_MAP_INTERLEAVE_NONE, CU_TENSOR_MAP_SWIZZLE_128B,
        CU_TENSOR_MAP_L2_PROMOTION_L2_128B, CU_TENSOR_MAP_FLOAT_OOB_FILL_NONE);
}

extern "C" void kernel_launch(void* const* d_in, const int* in_sizes, int n_in,
                              void* d_out, int out_size) {
    const float* x   = (const float*)d_in[0];
    const float* w0f = (const float*)d_in[1];
    const float* b0f = (const float*)d_in[2];
    const float* w0r = (const float*)d_in[3];
    const float* b0r = (const float*)d_in[4];
    const float* w1f = (const float*)d_in[5];
    const float* b1f = (const float*)d_in[6];
    const float* w1r = (const float*)d_in[7];
    const float* b1r = (const float*)d_in[8];
    float* out = (float*)d_out;

    void* p;
    cudaGetSymbolAddress(&p, g_xp0);   float* xp0   = (float*)p;
    cudaGetSymbolAddress(&p, g_xp1);   float* xp1   = (float*)p;
    cudaGetSymbolAddress(&p, g_gates); float* gates = (float*)p;
    cudaGetSymbolAddress(&p, g_wt0);   float* wt0   = (float*)p;
    cudaGetSymbolAddress(&p, g_wt1);   float* wt1   = (float*)p;

    void* pfn = nullptr;
    cudaDriverEntryPointQueryResult qres;
    cudaGetDriverEntryPoint("cuTensorMapEncodeTiled", &pfn, cudaEnableDefault, &qres);
    EncodeFn enc = (EncodeFn)pfn;

    CUtensorMap tA0, tB0, tA1, tB1;
    make2d(enc, &tA0, xp0, D0, (uint64_t)BQ * LP, 128);   // A box [32,128]
    make2d(enc, &tB0, wt0, 3 * D0, NG2, 128);             // B half-slices [32,128]
    make2d(enc, &tA1, xp1, D1, (uint64_t)BQ * LP, 128);
    make2d(enc, &tB1, wt1, 3 * D1, NG2, 128);

    const int SMEM_TC = 1024 + 3 * (int)STAGE;  // 148480
    cudaFuncSetAttribute(gemm_tc, cudaFuncAttributeMaxDynamicSharedMemorySize, SMEM_TC);
    cudaFuncSetAttribute(gemm_legacy, cudaFuncAttributeMaxDynamicSharedMemorySize, 65536);

    const size_t OUT2 = (size_t)BQ * LQ * 1024;
    float* h1 = out + OUT2;
    float* h2 = h1 + BQ * 1024;
    float* c1 = h2 + BQ * 1024;
    float* c2 = c1 + BQ * 1024;

    const int NPAIR = NTILE * 128;   // 1536 pair-tiles (128 M-pairs x 12 N-tiles)
    dim3 lgrid(24, 256);

    // ordering keeps gemm_tc at profiled index 5 (+2 harness launches)
    pad_x_kernel<<<(BQ * LP * D0 + 255) / 256, 256>>>(x);                        // 0
    wtrans_kernel<<<NG2, 256>>>(w0f, w0r, wt0, D0);                              // 1
    gemm_legacy<<<lgrid, 256, 65536>>>(xp0, wt0, b0f, b0r, gates, D0, 9, 48);    // 2 (empty on 103a)
    gemm_tc<<<148, 320, SMEM_TC>>>(tA0, tB0, b0f, b0r, gates, 9, 48, NPAIR);     // 3
    zero_xp1_bounds_kernel<<<(BQ * 2 * D1 + 255) / 256, 256>>>();                // 4
    wtrans_kernel<<<NG2, 256>>>(w1f, w1r, wt1, D1);                              // 5
    scanA_kernel<<<1024, 256>>>(gates);                                          // 6
    scanB_kernel<<<64, 256>>>();                                                 // 7
    scanC_kernel<<<1024, 256>>>(gates, xp1, LP, 1, h1, c1, 1);                   // 8
    gemm_legacy<<<lgrid, 256, 65536>>>(xp1, wt1, b1f, b1r, gates, D1, 10, 96);   // 9 (empty on 103a)
    gemm_tc<<<148, 320, SMEM_TC>>>(tA1, tB1, b1f, b1r, gates, 10, 96, NPAIR);    // 10
    scanA_kernel<<<1024, 256>>>(gates);                                          // 11
    scanB_kernel<<<64, 256>>>();                                                 // 12
    scanC_kernel<<<1024, 256>>>(gates, out, LQ, 0, h2, c2, 0);                   // 13
}

// round 17
// speedup vs baseline: 1.5345x; 1.1175x over previous
#include <cuda_runtime.h>
#include <cuda.h>
#include <cstdint>

#define BQ 16
#define LQ 2048
#define LP 2050
#define OQ 512
#define NG 1536
#define NG2 3072
#define D0 512
#define D1 1024
#define NTILE 12
#define STAGE 49152u
#define NSTG 4

#if defined(__CUDA_ARCH_FEAT_SM103_ALL) || defined(__CUDA_ARCH_FEAT_SM100_ALL)
#define HAS_TCGEN05 1
#else
#define HAS_TCGEN05 0
#endif

// ---------------- device scratch ----------------
static __device__ float g_xp0[(size_t)BQ * LP * D0];
static __device__ float g_xp1[(size_t)BQ * LP * D1];
static __device__ float g_gates[(size_t)BQ * LQ * NG2];
static __device__ float g_wt0[(size_t)NG2 * 3 * D0];
static __device__ float g_wt1[(size_t)NG2 * 3 * D1];
static __device__ float g_P[262144];
static __device__ float g_Q[262144];
static __device__ float g_cin[262144];

__device__ __forceinline__ float tf32r(float v) {
    uint32_t u;
    asm("cvt.rna.tf32.f32 %0, %1;" : "=r"(u) : "f"(v));
    return __uint_as_float(u);
}
__device__ __forceinline__ float sig_f(float x) {
    return __fdividef(1.f, 1.f + __expf(-x));
}
__device__ __forceinline__ float tanh_f(float x) {
    return __fdividef(2.f, 1.f + __expf(-2.f * x)) - 1.f;
}

// ---------------- setup kernels ----------------
__global__ void pad_x_kernel(const float* __restrict__ x) {
    int idx = blockIdx.x * blockDim.x + threadIdx.x;
    if (idx >= BQ * LP * D0) return;
    int b = idx / (LP * D0);
    int rem = idx - b * (LP * D0);
    int tt = rem >> 9;
    int c = rem & 511;
    float v = 0.f;
    if (tt >= 1 && tt <= LQ) v = x[((size_t)b * LQ + (tt - 1)) * D0 + c];
    g_xp0[idx] = tf32r(v);
}

__global__ void zero_xp1_bounds_kernel() {
    int idx = blockIdx.x * blockDim.x + threadIdx.x;
    if (idx >= BQ * 2 * D1) return;
    int b = idx / (2 * D1);
    int r = (idx >> 10) & 1;
    int c = idx & 1023;
    g_xp1[((size_t)b * LP + (r ? (LP - 1) : 0)) * D1 + c] = 0.f;
}

__global__ void __launch_bounds__(256) wtrans_kernel(const float* __restrict__ wf,
                                                     const float* __restrict__ wr,
                                                     float* __restrict__ dst, int Din) {
    __shared__ float smt[3072];
    int row = blockIdx.x;
    int K3 = 3 * Din;
    const float* w = (row < NG) ? wf : wr;
    int oc = (row < NG) ? row : row - NG;
    const float* src = w + (size_t)oc * K3;
    for (int j2 = threadIdx.x; j2 < K3; j2 += 256) {
        int i = j2 / 3;
        int k = j2 - 3 * i;
        smt[k * Din + i] = tf32r(src[j2]);
    }
    __syncthreads();
    float* drow = dst + (size_t)row * K3;
    for (int j = threadIdx.x; j < K3; j += 256) drow[j] = smt[j];
}

// ---------------- ptx helpers ----------------
__device__ __forceinline__ uint32_t elect1() {
    uint32_t p;
    asm volatile("{ .reg .pred p; elect.sync _|p, 0xFFFFFFFF; selp.b32 %0, 1, 0, p; }" : "=r"(p));
    return p;
}
__device__ __forceinline__ uint32_t ctarank() {
    uint32_t r;
    asm("mov.u32 %0, %%cluster_ctarank;" : "=r"(r));
    return r;
}
__device__ __forceinline__ void mbar_init(uint32_t a, uint32_t c) {
    asm volatile("mbarrier.init.shared.b64 [%0], %1;" ::"r"(a), "r"(c) : "memory");
}
__device__ __forceinline__ void mbar_arrive(uint32_t a) {
    asm volatile("mbarrier.arrive.shared.b64 _, [%0];" ::"r"(a) : "memory");
}
__device__ __forceinline__ void mbar_expect(uint32_t a, uint32_t b) {
    asm volatile("mbarrier.arrive.expect_tx.shared.b64 _, [%0], %1;" ::"r"(a), "r"(b) : "memory");
}
__device__ __forceinline__ void mbar_wait(uint32_t a, uint32_t ph) {
    asm volatile(
        "{ .reg .pred P; LW_%=: mbarrier.try_wait.parity.acquire.cta.shared::cta.b64 P, [%0], %1, 0x989680;"
        " @P bra LD_%=; bra LW_%=; LD_%=: }" ::"r"(a), "r"(ph) : "memory");
}
__device__ __forceinline__ void mbar_wait_rlx(uint32_t a, uint32_t ph) {
    asm volatile(
        "{ .reg .pred P; LW_%=: mbarrier.try_wait.parity.relaxed.cta.shared::cta.b64 P, [%0], %1, 0x989680;"
        " @P bra LD_%=; bra LW_%=; LD_%=: }" ::"r"(a), "r"(ph) : "memory");
}
__device__ __forceinline__ void tma2d(uint32_t dst, const CUtensorMap* tm, int x, int y, uint32_t mbar) {
    asm volatile(
        "cp.async.bulk.tensor.2d.shared::cta.global.tile.mbarrier::complete_tx::bytes "
        "[%0], [%1, {%2, %3}], [%4];" ::"r"(dst), "l"(tm), "r"(x), "r"(y), "r"(mbar)
        : "memory");
}
__device__ __forceinline__ uint64_t mkdesc(uint32_t addr) {
    // SW128, version=1, SBO=64 (1024B), LBO=1 (16B)
    return 0x4000404000010000ULL | ((uint64_t)(addr >> 4) & 0x3FFF);
}
// tf32 idesc: dtype=F32, a/b=TF32, M=128, N=256
#define IDESC_TF32 0x8400910u
#define CLUSTER_SYNC_()                                                 \
    do {                                                                \
        asm volatile("barrier.cluster.arrive.aligned;" ::: "memory");   \
        asm volatile("barrier.cluster.wait.aligned;" ::: "memory");     \
    } while (0)

#if HAS_TCGEN05
__device__ __forceinline__ void tma2d_mc(uint32_t dst, const CUtensorMap* tm, int x, int y,
                                         uint32_t mbar, uint16_t mask) {
    asm volatile(
        "cp.async.bulk.tensor.2d.shared::cluster.global.tile.mbarrier::complete_tx::bytes.multicast::cluster "
        "[%0], [%1, {%2, %3}], [%4], %5;" ::"r"(dst), "l"(tm), "r"(x), "r"(y), "r"(mbar), "h"(mask)
        : "memory");
}
__device__ __forceinline__ void mma_tf32_tc(uint32_t d, uint64_t ad, uint64_t bd, bool acc) {
    uint32_t en = acc ? 1u : 0u;
    asm volatile(
        "{\n\t.reg .pred p;\n\tsetp.ne.u32 p, %4, 0;\n\t"
        "tcgen05.mma.cta_group::1.kind::tf32 [%0], %1, %2, %3, {%5,%5,%5,%5}, p;\n\t}"
        ::"r"(d), "l"(ad), "l"(bd), "r"(IDESC_TF32), "r"(en), "r"(0u)
        : "memory");
}
#define TALLOC(sa, n) asm volatile("tcgen05.alloc.cta_group::1.sync.aligned.shared::cta.b32 [%0], %1;" ::"r"(sa), "r"(n) : "memory")
#define TDEALLOC(t, n) asm volatile("tcgen05.dealloc.cta_group::1.sync.aligned.b32 %0, %1;" ::"r"(t), "r"(n))
#define TRELINQ() asm volatile("tcgen05.relinquish_alloc_permit.cta_group::1.sync.aligned;")
#define TCOMMIT(a) asm volatile("tcgen05.commit.cta_group::1.mbarrier::arrive::one.shared::cluster.b64 [%0];" ::"r"(a) : "memory")
#define TCOMMIT_MC(a, m) asm volatile("tcgen05.commit.cta_group::1.mbarrier::arrive::one.shared::cluster.multicast::cluster.b64 [%0], %1;" ::"r"(a), "h"((uint16_t)(m)) : "memory")
#define TFENCE_AFTER() asm volatile("tcgen05.fence::after_thread_sync;" ::: "memory")
#define TFENCE_BEFORE() asm volatile("tcgen05.fence::before_thread_sync;" ::: "memory")
#define TWAIT_LD() asm volatile("tcgen05.wait::ld.sync.aligned;" ::: "memory")
#define TLD_X32(r, a)                                                                           \
    asm volatile(                                                                               \
        "tcgen05.ld.sync.aligned.32x32b.x32.b32 "                                               \
        "{%0, %1, %2, %3, %4, %5, %6, %7, %8, %9, %10, %11, %12, %13, %14, %15, "               \
        " %16, %17, %18, %19, %20, %21, %22, %23, %24, %25, %26, %27, %28, %29, %30, %31}, "    \
        "[%32];"                                                                                \
        : "=r"((r)[0]), "=r"((r)[1]), "=r"((r)[2]), "=r"((r)[3]), "=r"((r)[4]), "=r"((r)[5]),   \
          "=r"((r)[6]), "=r"((r)[7]), "=r"((r)[8]), "=r"((r)[9]), "=r"((r)[10]), "=r"((r)[11]), \
          "=r"((r)[12]), "=r"((r)[13]), "=r"((r)[14]), "=r"((r)[15]), "=r"((r)[16]),            \
          "=r"((r)[17]), "=r"((r)[18]), "=r"((r)[19]), "=r"((r)[20]), "=r"((r)[21]),            \
          "=r"((r)[22]), "=r"((r)[23]), "=r"((r)[24]), "=r"((r)[25]), "=r"((r)[26]),            \
          "=r"((r)[27]), "=r"((r)[28]), "=r"((r)[29]), "=r"((r)[30]), "=r"((r)[31])             \
        : "r"(a))
#endif

// =====================================================================
// PATH A: persistent tcgen05 tf32 GEMM, TMEM double-buffered epilogue,
// cluster(2,1,1) B-multicast pairs, now with a 4-STAGE TMA ring to test
// (and fix) TMA-latency exposure. Tile M=128 x N=256, K-tile 32 (SW128).
// Stage = A16K + B32K, x4 stages = 192KB.
// =====================================================================
__global__ void __launch_bounds__(320, 1) __cluster_dims__(2, 1, 1) gemm_tc(
    const __grid_constant__ CUtensorMap dA,
    const __grid_constant__ CUtensorMap dB,
    const float* __restrict__ bf, const float* __restrict__ br,
    float* __restrict__ G, int DinLog, int numKt, int numPairs) {
#if HAS_TCGEN05
    extern __shared__ char smem[];
    uint32_t sb = (uint32_t)__cvta_generic_to_shared(smem);
    const uint32_t TMEMP = sb;
    const uint32_t BARB = sb + 16;    // full[s]=+s*16, empty[s]=+s*16+8 (4 stages)
    const uint32_t DONE = sb + 96;    // done[buf] = +buf*8
    const uint32_t EFREE = sb + 112;  // efree[buf] = +buf*8
    const uint32_t SA = sb + 1024;    // stage: A 16K | B 32K

    int tid = threadIdx.x, lane = tid & 31, wid = tid >> 5;
    int Din = 1 << DinLog;
    uint32_t rank = ctarank();
    int pair = blockIdx.x >> 1;
    int pstep = gridDim.x >> 1;

    if (tid == 0) {
        for (int s = 0; s < NSTG; s++) {
            mbar_init(BARB + s * 16, 1);       // full: tx-driven
            mbar_init(BARB + s * 16 + 8, 2);   // empty: commit-MC from both ranks
        }
        mbar_init(DONE, 1);
        mbar_init(DONE + 8, 1);
        mbar_init(EFREE, 1);
        mbar_init(EFREE + 8, 1);
    }
    if (wid == 9) TALLOC(TMEMP, 512);
    __syncthreads();
    CLUSTER_SYNC_();                  // peer mbarriers live before multicast
    uint32_t tmem;
    asm volatile("ld.shared.b32 %0, [%1];" : "=r"(tmem) : "r"(TMEMP));

    if (wid == 8) {                       // TMA producer
        if (elect1()) {
            int ph = 1, s = 0;
            for (int tp = pair; tp < numPairs; tp += pstep) {
                int m0 = ((tp / NTILE) << 8) + (int)rank * 128;
                int n0 = (tp % NTILE) << 8;
                int Rbase = (m0 >> 11) * LP + (m0 & 2047);
                for (int kt = 0; kt < numKt; kt++) {
                    mbar_wait_rlx(BARB + s * 16 + 8, ph);
                    mbar_expect(BARB + s * 16, STAGE);   // A16K + ownB16K + peerB16K
                    int j0 = kt << 5;
                    int q = j0 >> DinLog, r = j0 & (Din - 1);
                    uint32_t st = SA + s * STAGE;
                    tma2d(st, &dA, r, Rbase + q, BARB + s * 16);
                    tma2d_mc(st + 16384u + rank * 16384u, &dB, j0, n0 + (int)rank * 128,
                             BARB + s * 16, 0x3);
                    if (++s == NSTG) { s = 0; ph ^= 1; }
                }
            }
        }
    } else if (wid == 9) {                // MMA issuer with tile double-buffer
        if (elect1()) {
            int phF = 0, s = 0;
            int phE0 = 1, phE1 = 1;
            int i = 0;
            for (int tp = pair; tp < numPairs; tp += pstep, i++) {
                int buf = i & 1;
                if (buf == 0) { mbar_wait_rlx(EFREE, phE0); phE0 ^= 1; }
                else          { mbar_wait_rlx(EFREE + 8, phE1); phE1 ^= 1; }
                TFENCE_AFTER();
                uint32_t dbase = tmem + buf * 256;
                for (int kt = 0; kt < numKt; kt++) {
                    mbar_wait_rlx(BARB + s * 16, phF);
                    uint32_t st = SA + s * STAGE;
                    uint64_t ad = mkdesc(st);
                    uint64_t bd = mkdesc(st + 16384u);
#pragma unroll
                    for (int ks = 0; ks < 4; ks++) {
                        bool acc = (kt | ks) != 0;
                        mma_tf32_tc(dbase, ad + ks * 2, bd + ks * 2, acc);
                    }
                    TCOMMIT_MC(BARB + s * 16 + 8, 0x3);   // free stage in BOTH CTAs
                    if (++s == NSTG) { s = 0; phF ^= 1; }
                }
                TCOMMIT(DONE + buf * 8);
            }
        }
    }

    if (wid < 8) {                        // epilogue: drain prev tile's buffer
        int phD0 = 0, phD1 = 0;
        int nhalf = wid >> 2;
        int i = 0;
        for (int tp = pair; tp < numPairs; tp += pstep, i++) {
            int buf = i & 1;
            if (buf == 0) { mbar_wait(DONE, phD0); phD0 ^= 1; }
            else          { mbar_wait(DONE + 8, phD1); phD1 ^= 1; }
            TFENCE_AFTER();
            int m0 = ((tp / NTILE) << 8) + (int)rank * 128;
            int n0 = (tp % NTILE) << 8;
            int mrow = m0 + (wid & 3) * 32 + lane;
            float* grow = G + (size_t)mrow * NG2;
#pragma unroll 1
            for (int cb = 0; cb < 4; cb++) {
                uint32_t r[32];
                TLD_X32(r, tmem + buf * 256 + nhalf * 128 + cb * 32);
                TWAIT_LD();
                int nb = n0 + nhalf * 128 + cb * 32;
                int cmod = (nb >= NG) ? nb - NG : nb;
                const float* bias = (nb >= NG) ? (br + cmod) : (bf + cmod);
                bool ist = cmod >= 2 * OQ;
#pragma unroll
                for (int j = 0; j < 32; j += 4) {
                    float v0 = __uint_as_float(r[j + 0]) + bias[j + 0];
                    float v1 = __uint_as_float(r[j + 1]) + bias[j + 1];
                    float v2 = __uint_as_float(r[j + 2]) + bias[j + 2];
                    float v3 = __uint_as_float(r[j + 3]) + bias[j + 3];
                    float4 o4;
                    o4.x = ist ? tanh_f(v0) : sig_f(v0);
                    o4.y = ist ? tanh_f(v1) : sig_f(v1);
                    o4.z = ist ? tanh_f(v2) : sig_f(v2);
                    o4.w = ist ? tanh_f(v3) : sig_f(v3);
                    *(float4*)(grow + nb + j) = o4;
                }
            }
            TFENCE_BEFORE();
            asm volatile("bar.sync 1, 256;" ::: "memory");
            if (tid == 0) mbar_arrive(EFREE + buf * 8);
        }
    }
    __syncthreads();
    CLUSTER_SYNC_();                  // no exit while peer multicast in flight
    if (wid == 9) {
        TRELINQ();
        TDEALLOC(tmem, 512);
    }
#endif  // HAS_TCGEN05
}

// =====================================================================
// PATH B: legacy mma.sync tf32 GEMM (fallback when no 103a PTX)
// =====================================================================
__device__ __forceinline__ void mma_tf32_leg(float* d, const uint32_t* a, const uint32_t* b) {
    asm volatile(
        "mma.sync.aligned.m16n8k8.row.col.f32.tf32.tf32.f32 "
        "{%0,%1,%2,%3}, {%4,%5,%6,%7}, {%8,%9}, {%0,%1,%2,%3};"
        : "+f"(d[0]), "+f"(d[1]), "+f"(d[2]), "+f"(d[3])
        : "r"(a[0]), "r"(a[1]), "r"(a[2]), "r"(a[3]), "r"(b[0]), "r"(b[1]));
}

__global__ void __launch_bounds__(256, 2) gemm_legacy(
    const float* __restrict__ A, const float* __restrict__ W,
    const float* __restrict__ bf, const float* __restrict__ br,
    float* __restrict__ G, int Din, int DinLog, int numKt) {
#if !HAS_TCGEN05
    extern __shared__ float sm[];
    const int K3 = Din * 3;
    int tid = threadIdx.x, lane = tid & 31, warp = tid >> 5;
    int wm = warp >> 2, wn = warp & 3;
    int m0 = blockIdx.y << 7, n0 = blockIdx.x << 7;
    int bb = m0 >> 11, t0 = m0 & 2047;
    size_t Rbase = (size_t)bb * LP + t0;
    uint32_t sbase = (uint32_t)__cvta_generic_to_shared(sm);

    float acc[4][4][4];
#pragma unroll
    for (int i = 0; i < 4; i++)
#pragma unroll
        for (int j = 0; j < 4; j++)
#pragma unroll
            for (int k = 0; k < 4; k++) acc[i][j][k] = 0.f;

    auto load_tiles = [&](int s, int kt) {
        int j0 = kt << 5;
        int q = j0 >> DinLog, r = j0 & (Din - 1);
        const float* Ab = A + (Rbase + q) * (size_t)Din + r;
        const float* Bb = W + j0;
        uint32_t aoff = sbase + s * 16384u;
        uint32_t boff = sbase + 32768u + s * 16384u;
#pragma unroll
        for (int u = 0; u < 4; u++) {
            int idx2 = (u << 8) + tid;
            int row = idx2 >> 3, g4 = idx2 & 7;
            uint32_t d = (uint32_t)((row << 5) + ((g4 ^ (row & 7)) << 2)) * 4u;
            const float* sa = Ab + (size_t)row * Din + (g4 << 2);
            const float* sb2 = Bb + (size_t)(n0 + row) * K3 + (g4 << 2);
            asm volatile("cp.async.cg.shared.global [%0], [%1], 16;" ::"r"(aoff + d), "l"(sa));
            asm volatile("cp.async.cg.shared.global [%0], [%1], 16;" ::"r"(boff + d), "l"(sb2));
        }
    };

    load_tiles(0, 0);
    asm volatile("cp.async.commit_group;");
    int r4 = lane >> 2, c4 = lane & 3;

    for (int kt = 0; kt < numKt; kt++) {
        int cur = kt & 1;
        if (kt + 1 < numKt) {
            load_tiles(cur ^ 1, kt + 1);
            asm volatile("cp.async.commit_group;");
            asm volatile("cp.async.wait_group 1;");
        } else {
            asm volatile("cp.async.wait_group 0;");
        }
        __syncthreads();
        const float* As_ = sm + cur * 4096;
        const float* Bs_ = sm + 8192 + cur * 4096;
#pragma unroll
        for (int kk = 0; kk < 4; kk++) {
            int g0 = ((2 * kk) ^ r4) << 2, g1 = ((2 * kk + 1) ^ r4) << 2;
            uint32_t a[4][4], bq[4][2];
#pragma unroll
            for (int mi = 0; mi < 4; mi++) {
                int row = (wm << 6) + (mi << 4) + r4;
                a[mi][0] = __float_as_uint(As_[(row << 5) + g0 + c4]);
                a[mi][1] = __float_as_uint(As_[((row + 8) << 5) + g0 + c4]);
                a[mi][2] = __float_as_uint(As_[(row << 5) + g1 + c4]);
                a[mi][3] = __float_as_uint(As_[((row + 8) << 5) + g1 + c4]);
            }
#pragma unroll
            for (int ni = 0; ni < 4; ni++) {
                int row = (wn << 5) + (ni << 3) + r4;
                bq[ni][0] = __float_as_uint(Bs_[(row << 5) + g0 + c4]);
                bq[ni][1] = __float_as_uint(Bs_[(row << 5) + g1 + c4]);
            }
#pragma unroll
            for (int mi = 0; mi < 4; mi++)
#pragma unroll
                for (int ni = 0; ni < 4; ni++) mma_tf32_leg(acc[mi][ni], a[mi], bq[ni]);
        }
        __syncthreads();
    }

#pragma unroll
    for (int mi = 0; mi < 4; mi++) {
        int mrow = m0 + (wm << 6) + (mi << 4) + r4;
#pragma unroll
        for (int ni = 0; ni < 4; ni++) {
            int n = n0 + (wn << 5) + (ni << 3) + (c4 << 1);
            int cmod = (n >= NG) ? n - NG : n;
            float bias0 = (n >= NG) ? br[n - NG] : bf[n];
            float bias1 = (n >= NG) ? br[n - NG + 1] : bf[n + 1];
            float v0 = acc[mi][ni][0] + bias0;
            float v1 = acc[mi][ni][1] + bias1;
            float v2 = acc[mi][ni][2] + bias0;
            float v3 = acc[mi][ni][3] + bias1;
            bool is_tanh = (cmod >= 2 * OQ);
            float a0 = is_tanh ? tanh_f(v0) : sig_f(v0);
            float a1 = is_tanh ? tanh_f(v1) : sig_f(v1);
            float a2 = is_tanh ? tanh_f(v2) : sig_f(v2);
            float a3 = is_tanh ? tanh_f(v3) : sig_f(v3);
            *(float2*)(G + (size_t)mrow * NG2 + n) = make_float2(a0, a1);
            *(float2*)(G + (size_t)(mrow + 8) * NG2 + n) = make_float2(a2, a3);
        }
    }
#endif  // !HAS_TCGEN05
}

// ---------------- 3-phase fo-pool scan (16x parallelism) ----------------
__global__ void __launch_bounds__(256) scanA_kernel(const float* __restrict__ Gt) {
    int idx = blockIdx.x * 256 + threadIdx.x;
    int chain = idx & 16383;
    int q = idx >> 14;
    int dir = chain >> 13, b = (chain >> 9) & 15, ch = chain & 511;
    const float* g = Gt + (size_t)b * LQ * NG2 + dir * NG + ch;
    float c = 0.f, Pp = 1.f;
    int s0 = q << 7;
    for (int su = 0; su < 128; su += 8) {
        float fv[8], zv[8];
#pragma unroll
        for (int u = 0; u < 8; u++) {
            int s = s0 + su + u;
            int t = dir ? (LQ - 1 - s) : s;
            size_t o = (size_t)t * NG2;
            fv[u] = g[o];
            zv[u] = g[o + 1024];
        }
#pragma unroll
        for (int u = 0; u < 8; u++) {
            Pp *= fv[u];
            c = fv[u] * (c - zv[u]) + zv[u];
        }
    }
    g_P[idx] = Pp;
    g_Q[idx] = c;
}

__global__ void __launch_bounds__(256) scanB_kernel() {
    int chain = blockIdx.x * 256 + threadIdx.x;
    float c = 0.f;
#pragma unroll
    for (int q = 0; q < 16; q++) {
        int id = (q << 14) + chain;
        g_cin[id] = c;
        c = g_P[id] * c + g_Q[id];
    }
}

__global__ void __launch_bounds__(256) scanC_kernel(
    const float* __restrict__ Gt, float* __restrict__ dst, int rowsPerB, int tOff,
    float* __restrict__ hdst, float* __restrict__ cdst, int doRound) {
    int idx = blockIdx.x * 256 + threadIdx.x;
    int chain = idx & 16383;
    int q = idx >> 14;
    int dir = chain >> 13, b = (chain >> 9) & 15, ch = chain & 511;
    const float* g = Gt + (size_t)b * LQ * NG2 + dir * NG + ch;
    int cc = (dir << 9) + ch;
    float* d = dst + ((size_t)b * rowsPerB + tOff) * 1024 + cc;
    float c = g_cin[idx];
    float hl = 0.f, cl = 0.f;
    int s0 = q << 7;
    for (int su = 0; su < 128; su += 8) {
        float fv[8], ov[8], zv[8];
#pragma unroll
        for (int u = 0; u < 8; u++) {
            int s = s0 + su + u;
            int t = dir ? (LQ - 1 - s) : s;
            size_t o = (size_t)t * NG2;
            fv[u] = g[o];
            ov[u] = g[o + 512];
            zv[u] = g[o + 1024];
        }
#pragma unroll
        for (int u = 0; u < 8; u++) {
            int s = s0 + su + u;
            int t = dir ? (LQ - 1 - s) : s;
            c = fv[u] * (c - zv[u]) + zv[u];
            float h = c * ov[u];
            d[(size_t)t * 1024] = doRound ? tf32r(h) : h;
            if ((dir == 0 && s == LQ - 1) || (dir == 1 && s == 0)) { hl = h; cl = c; }
        }
    }
    if ((dir == 0 && q == 15) || (dir == 1 && q == 0)) {
        hdst[b * 1024 + cc] = hl;
        cdst[b * 1024 + cc] = cl;
    }
}

// ---------------- host glue ----------------
typedef CUresult (*EncodeFn)(CUtensorMap*, CUtensorMapDataType, cuuint32_t, void*,
                             const cuuint64_t*, const cuuint64_t*, const cuuint32_t*,
                             const cuuint32_t*, CUtensorMapInterleave, CUtensorMapSwizzle,
                             CUtensorMapL2promotion, CUtensorMapFloatOOBfill);

static void make2d(EncodeFn enc, CUtensorMap* m, void* ptr, uint64_t dimx, uint64_t dimy,
                   uint32_t boxy) {
    cuuint64_t dims[2] = {dimx, dimy};
    cuuint64_t strides[1] = {dimx * 4};
    cuuint32_t box[2] = {32, boxy};
    cuuint32_t es[2] = {1, 1};
    enc(m, CU_TENSOR_MAP_DATA_TYPE_FLOAT32, 2, ptr, dims, strides, box, es,
        CU_TENSOR_MAP_INTERLEAVE_NONE, CU_TENSOR_MAP_SWIZZLE_128B,
        CU_TENSOR_MAP_L2_PROMOTION_L2_128B, CU_TENSOR_MAP_FLOAT_OOB_FILL_NONE);
}

extern "C" void kernel_launch(void* const* d_in, const int* in_sizes, int n_in,
                              void* d_out, int out_size) {
    const float* x   = (const float*)d_in[0];
    const float* w0f = (const float*)d_in[1];
    const float* b0f = (const float*)d_in[2];
    const float* w0r = (const float*)d_in[3];
    const float* b0r = (const float*)d_in[4];
    const float* w1f = (const float*)d_in[5];
    const float* b1f = (const float*)d_in[6];
    const float* w1r = (const float*)d_in[7];
    const float* b1r = (const float*)d_in[8];
    float* out = (float*)d_out;

    void* p;
    cudaGetSymbolAddress(&p, g_xp0);   float* xp0   = (float*)p;
    cudaGetSymbolAddress(&p, g_xp1);   float* xp1   = (float*)p;
    cudaGetSymbolAddress(&p, g_gates); float* gates = (float*)p;
    cudaGetSymbolAddress(&p, g_wt0);   float* wt0   = (float*)p;
    cudaGetSymbolAddress(&p, g_wt1);   float* wt1   = (float*)p;

    void* pfn = nullptr;
    cudaDriverEntryPointQueryResult qres;
    cudaGetDriverEntryPoint("cuTensorMapEncodeTiled", &pfn, cudaEnableDefault, &qres);
    EncodeFn enc = (EncodeFn)pfn;

    CUtensorMap tA0, tB0, tA1, tB1;
    make2d(enc, &tA0, xp0, D0, (uint64_t)BQ * LP, 128);   // A box [32,128]
    make2d(enc, &tB0, wt0, 3 * D0, NG2, 128);             // B half-slices [32,128]
    make2d(enc, &tA1, xp1, D1, (uint64_t)BQ * LP, 128);
    make2d(enc, &tB1, wt1, 3 * D1, NG2, 128);

    const int SMEM_TC = 1024 + NSTG * (int)STAGE;  // 197632
    cudaFuncSetAttribute(gemm_tc, cudaFuncAttributeMaxDynamicSharedMemorySize, SMEM_TC);
    cudaFuncSetAttribute(gemm_legacy, cudaFuncAttributeMaxDynamicSharedMemorySize, 65536);

    const size_t OUT2 = (size_t)BQ * LQ * 1024;
    float* h1 = out + OUT2;
    float* h2 = h1 + BQ * 1024;
    float* c1 = h2 + BQ * 1024;
    float* c2 = c1 + BQ * 1024;

    const int NPAIR = NTILE * 128;   // 1536 pair-tiles (128 M-pairs x 12 N-tiles)
    dim3 lgrid(24, 256);

    // ordering keeps gemm_tc at profiled index 5 (+2 harness launches)
    pad_x_kernel<<<(BQ * LP * D0 + 255) / 256, 256>>>(x);                        // 0
    wtrans_kernel<<<NG2, 256>>>(w0f, w0r, wt0, D0);                              // 1
    gemm_legacy<<<lgrid, 256, 65536>>>(xp0, wt0, b0f, b0r, gates, D0, 9, 48);    // 2 (empty on 103a)
    gemm_tc<<<148, 320, SMEM_TC>>>(tA0, tB0, b0f, b0r, gates, 9, 48, NPAIR);     // 3
    zero_xp1_bounds_kernel<<<(BQ * 2 * D1 + 255) / 256, 256>>>();                // 4
    wtrans_kernel<<<NG2, 256>>>(w1f, w1r, wt1, D1);                              // 5
    scanA_kernel<<<1024, 256>>>(gates);                                          // 6
    scanB_kernel<<<64, 256>>>();                                                 // 7
    scanC_kernel<<<1024, 256>>>(gates, xp1, LP, 1, h1, c1, 1);                   // 8
    gemm_legacy<<<lgrid, 256, 65536>>>(xp1, wt1, b1f, b1r, gates, D1, 10, 96);   // 9 (empty on 103a)
    gemm_tc<<<148, 320, SMEM_TC>>>(tA1, tB1, b1f, b1r, gates, 10, 96, NPAIR);    // 10
    scanA_kernel<<<1024, 256>>>(gates);                                          // 11
    scanB_kernel<<<64, 256>>>();                                                 // 12
    scanC_kernel<<<1024, 256>>>(gates, out, LQ, 0, h2, c2, 0);                   // 13
}